// round 7
// baseline (speedup 1.0000x reference)
#include <cuda_runtime.h>
#include <stdint.h>
#include <math.h>

#define Nn 4096
#define Hh 500
#define Dd 8
#define NHEADS 5
#define NG 2000      // 4 * Hh

#define BM 128
#define BN 128
#define BK 16
#define ASTRIDE 20    // 16 + 4 pad
#define BSTRIDE 132   // 128 + 4 pad
#define NKT 32        // ceil(500/16)

// ---------------- scratch (static device globals; no allocation) ----------------
__device__ float g_xA[Nn * Hh];
__device__ float g_xB[Nn * Hh];
__device__ float g_hA[Nn * Hh];
__device__ float g_hB[Nn * Hh];
__device__ float g_c[Nn * Hh];
__device__ float g_xw[(size_t)8 * Nn * NG];   // per-layer xWih for all 8 steps (262MB)
__device__ float g_wihp[Hh * NG];
__device__ float g_whhp[Hh * NG];
__device__ float g_bp[NG];
__device__ float g_z[Nn * NHEADS * Hh];
__device__ float g_el[Nn * NHEADS];
__device__ float g_er[Nn * NHEADS];

// ---------------- helpers ----------------
__device__ __forceinline__ float tf32r(float x) {
    unsigned int u;
    asm("cvt.rna.tf32.f32 %0, %1;" : "=r"(u) : "f"(x));
    return __uint_as_float(u);
}

__device__ __forceinline__ void mma_tf32(float c[4], float a0, float a1, float a2, float a3,
                                         float b0, float b1) {
    asm volatile(
        "mma.sync.aligned.m16n8k8.row.col.f32.tf32.tf32.f32 "
        "{%0,%1,%2,%3}, {%4,%5,%6,%7}, {%8,%9}, {%0,%1,%2,%3};"
        : "+f"(c[0]), "+f"(c[1]), "+f"(c[2]), "+f"(c[3])
        : "r"(__float_as_uint(a0)), "r"(__float_as_uint(a1)),
          "r"(__float_as_uint(a2)), "r"(__float_as_uint(a3)),
          "r"(__float_as_uint(b0)), "r"(__float_as_uint(b1)));
}

__device__ __forceinline__ float sigm(float x) { return 1.f / (1.f + expf(-x)); }

// ---------------- utility kernels ----------------
__global__ void zero_k(float* p, int n) {
    int i = blockIdx.x * blockDim.x + threadIdx.x;
    if (i < n) p[i] = 0.f;
}

__global__ void embed_k(const int* __restrict__ ids, const float* __restrict__ emb,
                        float* __restrict__ x) {
    int i = blockIdx.x * blockDim.x + threadIdx.x;
    if (i < Nn * Hh) {
        int n = i / Hh, c = i % Hh;
        x[i] = emb[ids[n] * Hh + c];
    }
}

// permute gate columns to interleaved layout (col = 4j+gate) + tf32 pre-round.
// src col = gate*500 + j.  Also builds combined interleaved bias.
__global__ void permute_w_k(const float* __restrict__ Wih, const float* __restrict__ Whh,
                            const float* __restrict__ bih, const float* __restrict__ bhh) {
    int idx = blockIdx.x * blockDim.x + threadIdx.x;
    if (idx >= Hh * NG) return;
    int k = idx / NG, cidx = idx % NG;
    int gate = cidx & 3, j = cidx >> 2;
    int src = k * NG + gate * Hh + j;
    g_wihp[idx] = tf32r(Wih[src]);
    g_whhp[idx] = tf32r(Whh[src]);
    if (k == 0) g_bp[cidx] = bih[gate * Hh + j] + bhh[gate * Hh + j];
}

// t=0 LSTM cell: gates = xw[0] (bias already included), c_prev = 0.
__global__ void cell0_k(const float* __restrict__ xw0, float* __restrict__ h0) {
    int i = blockIdx.x * blockDim.x + threadIdx.x;
    if (i >= Nn * Hh) return;
    int n = i / Hh, j = i % Hh;
    const float* gp = xw0 + (size_t)n * NG + 4 * j;
    float si = sigm(gp[0]);
    float gg = tanhf(gp[2]);
    float so = sigm(gp[3]);
    float c = si * gg;                 // sigm(f)*0 + sigm(i)*tanh(g)
    g_c[i] = c;
    h0[i] = tf32r(so * tanhf(c));
}

// ---------------- GEMM 1: xw precompute (M=32768 gather GEMM, interleaved cols) ----------------
// rows r = t*4096 + n;  A row = X[nbr[n*8+t]];  C[r][col] = A@Wihp + bp
__global__ __launch_bounds__(128, 2) void gemm_xw(
    const float* __restrict__ X, const int* __restrict__ nbr,
    float* __restrict__ Cout)
{
    __shared__ float As[2][BM * ASTRIDE];
    __shared__ float Bs[2][BK * BSTRIDE];

    const int tid = threadIdx.x;
    const int bm = blockIdx.y * BM;
    const int bn = blockIdx.x * BN;
    const int lane = tid & 31;
    const int warp = tid >> 5;
    const int g = lane >> 2, tig = lane & 3;
    const int am0 = (warp >> 1) * 64;
    const int bn0 = (warp & 1) * 64;
    const int brw = tid >> 3;
    const int bc0 = (tid & 7) * 16;

    const int t = bm >> 12;                 // 4096 rows per timestep
    const int n = (bm + tid) & (Nn - 1);
    const float* Arow = X + (size_t)nbr[n * Dd + t] * Hh;

    float acc[4][8][4];
#pragma unroll
    for (int mt = 0; mt < 4; mt++)
#pragma unroll
        for (int nt = 0; nt < 8; nt++)
#pragma unroll
            for (int r = 0; r < 4; r++) acc[mt][nt][r] = 0.f;

    float a_reg[16], b_reg[16];

    auto load_tile = [&](int kt) {
        const int k0 = kt * BK;
#pragma unroll
        for (int q = 0; q < 4; q++) {
            const int k = k0 + q * 4;
            if (k + 4 <= Hh) {
                float4 v = *reinterpret_cast<const float4*>(Arow + k);
                a_reg[q*4+0]=v.x; a_reg[q*4+1]=v.y; a_reg[q*4+2]=v.z; a_reg[q*4+3]=v.w;
            } else {
#pragma unroll
                for (int i = 0; i < 4; i++) a_reg[q*4+i] = (k + i < Hh) ? Arow[k + i] : 0.f;
            }
        }
        const int brow = k0 + brw;
        const bool rok = brow < Hh;
        const float* Bp = g_wihp + (size_t)brow * NG;
#pragma unroll
        for (int q = 0; q < 4; q++) {
            const int cb = bn + bc0 + q * 4;
            if (rok && cb + 4 <= NG) {
                float4 v = *reinterpret_cast<const float4*>(Bp + cb);
                b_reg[q*4+0]=v.x; b_reg[q*4+1]=v.y; b_reg[q*4+2]=v.z; b_reg[q*4+3]=v.w;
            } else {
#pragma unroll
                for (int i = 0; i < 4; i++)
                    b_reg[q*4+i] = (rok && cb + i < NG) ? Bp[cb + i] : 0.f;
            }
        }
    };
    auto store_tile = [&](int buf) {
        float* ap = &As[buf][tid * ASTRIDE];
#pragma unroll
        for (int i = 0; i < 16; i++) ap[i] = tf32r(a_reg[i]);   // x not pre-rounded
        float* bp = &Bs[buf][brw * BSTRIDE + bc0];
#pragma unroll
        for (int i = 0; i < 16; i++) bp[i] = b_reg[i];          // weights pre-rounded
    };

    load_tile(0);
    store_tile(0);
    __syncthreads();

    for (int tt = 0; tt < NKT; tt++) {
        const int buf = tt & 1;
        const bool more = (tt + 1 < NKT);
        if (more) load_tile(tt + 1);
        const float* Asb = As[buf];
        const float* Bsb = Bs[buf];
#pragma unroll
        for (int kk = 0; kk < 2; kk++) {
            const int k8 = kk * 8;
            float fa0[4], fa1[4], fa2[4], fa3[4];
#pragma unroll
            for (int mt = 0; mt < 4; mt++) {
                const int r = am0 + mt * 16 + g;
                fa0[mt] = Asb[r * ASTRIDE + k8 + tig];
                fa1[mt] = Asb[(r + 8) * ASTRIDE + k8 + tig];
                fa2[mt] = Asb[r * ASTRIDE + k8 + tig + 4];
                fa3[mt] = Asb[(r + 8) * ASTRIDE + k8 + tig + 4];
            }
            float fb0[8], fb1[8];
#pragma unroll
            for (int nt = 0; nt < 8; nt++) {
                const int cn = bn0 + nt * 8 + g;
                fb0[nt] = Bsb[(k8 + tig) * BSTRIDE + cn];
                fb1[nt] = Bsb[(k8 + tig + 4) * BSTRIDE + cn];
            }
#pragma unroll
            for (int mt = 0; mt < 4; mt++)
#pragma unroll
                for (int nt = 0; nt < 8; nt++)
                    mma_tf32(acc[mt][nt], fa0[mt], fa1[mt], fa2[mt], fa3[mt],
                             fb0[nt], fb1[nt]);
        }
        if (more) store_tile(buf ^ 1);
        __syncthreads();
    }

#pragma unroll
    for (int mt = 0; mt < 4; mt++) {
        const size_t row0 = bm + am0 + mt * 16 + g;
#pragma unroll
        for (int nt = 0; nt < 8; nt++) {
            const int col = bn + bn0 + nt * 8 + 2 * tig;
            if (col < NG) {
                float ba = g_bp[col], bb = g_bp[col + 1];
                *reinterpret_cast<float2*>(&Cout[row0 * NG + col]) =
                    make_float2(acc[mt][nt][0] + ba, acc[mt][nt][1] + bb);
                *reinterpret_cast<float2*>(&Cout[(row0 + 8) * NG + col]) =
                    make_float2(acc[mt][nt][2] + ba, acc[mt][nt][3] + bb);
            }
        }
    }
}

// ---------------- GEMM 2: h@Whh + xw[t] with fused LSTM cell epilogue ----------------
__global__ __launch_bounds__(128, 2) void gemm_hcell(
    const float* __restrict__ Hin, const float* __restrict__ XWt,
    float* __restrict__ Hout)
{
    __shared__ float As[2][BM * ASTRIDE];
    __shared__ float Bs[2][BK * BSTRIDE];

    const int tid = threadIdx.x;
    const int bm = blockIdx.y * BM;
    const int bn = blockIdx.x * BN;
    const int lane = tid & 31;
    const int warp = tid >> 5;
    const int g = lane >> 2, tig = lane & 3;
    const int am0 = (warp >> 1) * 64;
    const int bn0 = (warp & 1) * 64;
    const int brw = tid >> 3;
    const int bc0 = (tid & 7) * 16;

    const float* Arow = Hin + (size_t)(bm + tid) * Hh;

    float acc[4][8][4];
#pragma unroll
    for (int mt = 0; mt < 4; mt++)
#pragma unroll
        for (int nt = 0; nt < 8; nt++)
#pragma unroll
            for (int r = 0; r < 4; r++) acc[mt][nt][r] = 0.f;

    float a_reg[16], b_reg[16];

    auto load_tile = [&](int kt) {
        const int k0 = kt * BK;
#pragma unroll
        for (int q = 0; q < 4; q++) {
            const int k = k0 + q * 4;
            if (k + 4 <= Hh) {
                float4 v = *reinterpret_cast<const float4*>(Arow + k);
                a_reg[q*4+0]=v.x; a_reg[q*4+1]=v.y; a_reg[q*4+2]=v.z; a_reg[q*4+3]=v.w;
            } else {
#pragma unroll
                for (int i = 0; i < 4; i++) a_reg[q*4+i] = (k + i < Hh) ? Arow[k + i] : 0.f;
            }
        }
        const int brow = k0 + brw;
        const bool rok = brow < Hh;
        const float* Bp = g_whhp + (size_t)brow * NG;
#pragma unroll
        for (int q = 0; q < 4; q++) {
            const int cb = bn + bc0 + q * 4;
            if (rok && cb + 4 <= NG) {
                float4 v = *reinterpret_cast<const float4*>(Bp + cb);
                b_reg[q*4+0]=v.x; b_reg[q*4+1]=v.y; b_reg[q*4+2]=v.z; b_reg[q*4+3]=v.w;
            } else {
#pragma unroll
                for (int i = 0; i < 4; i++)
                    b_reg[q*4+i] = (rok && cb + i < NG) ? Bp[cb + i] : 0.f;
            }
        }
    };
    auto store_tile = [&](int buf) {
        float* ap = &As[buf][tid * ASTRIDE];
#pragma unroll
        for (int i = 0; i < 16; i++) ap[i] = a_reg[i];          // h pre-rounded
        float* bp = &Bs[buf][brw * BSTRIDE + bc0];
#pragma unroll
        for (int i = 0; i < 16; i++) bp[i] = b_reg[i];          // weights pre-rounded
    };

    load_tile(0);
    store_tile(0);
    __syncthreads();

    for (int tt = 0; tt < NKT; tt++) {
        const int buf = tt & 1;
        const bool more = (tt + 1 < NKT);
        if (more) load_tile(tt + 1);
        const float* Asb = As[buf];
        const float* Bsb = Bs[buf];
#pragma unroll
        for (int kk = 0; kk < 2; kk++) {
            const int k8 = kk * 8;
            float fa0[4], fa1[4], fa2[4], fa3[4];
#pragma unroll
            for (int mt = 0; mt < 4; mt++) {
                const int r = am0 + mt * 16 + g;
                fa0[mt] = Asb[r * ASTRIDE + k8 + tig];
                fa1[mt] = Asb[(r + 8) * ASTRIDE + k8 + tig];
                fa2[mt] = Asb[r * ASTRIDE + k8 + tig + 4];
                fa3[mt] = Asb[(r + 8) * ASTRIDE + k8 + tig + 4];
            }
            float fb0[8], fb1[8];
#pragma unroll
            for (int nt = 0; nt < 8; nt++) {
                const int cn = bn0 + nt * 8 + g;
                fb0[nt] = Bsb[(k8 + tig) * BSTRIDE + cn];
                fb1[nt] = Bsb[(k8 + tig + 4) * BSTRIDE + cn];
            }
#pragma unroll
            for (int mt = 0; mt < 4; mt++)
#pragma unroll
                for (int nt = 0; nt < 8; nt++)
                    mma_tf32(acc[mt][nt], fa0[mt], fa1[mt], fa2[mt], fa3[mt],
                             fb0[nt], fb1[nt]);
        }
        if (more) store_tile(buf ^ 1);
        __syncthreads();
    }

    // ---- fused LSTM cell epilogue ----
    // cols interleaved: 4j+gate. Thread (tig even) holds (i,f); neighbor lane^1 holds (g,o).
#pragma unroll
    for (int mt = 0; mt < 4; mt++) {
        const int row0 = bm + am0 + mt * 16 + g;
#pragma unroll
        for (int nt = 0; nt < 8; nt++) {
            const int col = bn + bn0 + nt * 8 + 2 * tig;
            const bool ok = col < NG;                 // uniform per 8-col chunk (NG%8==0)
            float v0 = 0.f, v1 = 0.f, v2 = 0.f, v3 = 0.f;
            if (ok) {
                float2 x0 = *reinterpret_cast<const float2*>(&XWt[(size_t)row0 * NG + col]);
                float2 x1 = *reinterpret_cast<const float2*>(&XWt[(size_t)(row0 + 8) * NG + col]);
                v0 = acc[mt][nt][0] + x0.x;
                v1 = acc[mt][nt][1] + x0.y;
                v2 = acc[mt][nt][2] + x1.x;
                v3 = acc[mt][nt][3] + x1.y;
            }
            float gg0 = __shfl_xor_sync(0xFFFFFFFFu, v0, 1);
            float oo0 = __shfl_xor_sync(0xFFFFFFFFu, v1, 1);
            float gg1 = __shfl_xor_sync(0xFFFFFFFFu, v2, 1);
            float oo1 = __shfl_xor_sync(0xFFFFFFFFu, v3, 1);
            if (ok && (tig & 1) == 0) {
                const int j = col >> 2;
                {
                    float cp = g_c[row0 * Hh + j];
                    float c = sigm(v1) * cp + sigm(v0) * tanhf(gg0);
                    g_c[row0 * Hh + j] = c;
                    Hout[(size_t)row0 * Hh + j] = tf32r(sigm(oo0) * tanhf(c));
                }
                {
                    const int r1 = row0 + 8;
                    float cp = g_c[r1 * Hh + j];
                    float c = sigm(v3) * cp + sigm(v2) * tanhf(gg1);
                    g_c[r1 * Hh + j] = c;
                    Hout[(size_t)r1 * Hh + j] = tf32r(sigm(oo1) * tanhf(c));
                }
            }
        }
    }
}

// ---------------- generic GEMM (fc + GAT z), unchanged from round 6 ----------------
__global__ __launch_bounds__(128, 2) void gemm_mma(
    const float* __restrict__ X0, const int* __restrict__ nbr, int t,
    const float* __restrict__ X1,
    const float* __restrict__ B0, const float* __restrict__ B1,
    const float* __restrict__ bias0, const float* __restrict__ bias1,
    float* __restrict__ C, int Ncols, int act)
{
    __shared__ float As[2][BM * ASTRIDE];
    __shared__ float Bs[2][BK * BSTRIDE];

    const int tid = threadIdx.x;
    const int bm = blockIdx.y * BM;
    const int bn = blockIdx.x * BN;
    const int lane = tid & 31;
    const int warp = tid >> 5;
    const int g = lane >> 2, tig = lane & 3;
    const int am0 = (warp >> 1) * 64;
    const int bn0 = (warp & 1) * 64;
    const int brw = tid >> 3;
    const int bc0 = (tid & 7) * 16;

    const int arow0 = nbr ? nbr[(bm + tid) * Dd + t] : (bm + tid);
    const float* Arow0 = X0 + (size_t)arow0 * Hh;
    const float* Arow1 = X1 ? (X1 + (size_t)(bm + tid) * Hh) : nullptr;
    const int ntiles = (X1 ? 2 : 1) * NKT;

    float acc[4][8][4];
#pragma unroll
    for (int mt = 0; mt < 4; mt++)
#pragma unroll
        for (int nt = 0; nt < 8; nt++)
#pragma unroll
            for (int r = 0; r < 4; r++) acc[mt][nt][r] = 0.f;

    float a_reg[16], b_reg[16];

    auto load_tile = [&](int tt) {
        const int part = (tt >= NKT) ? 1 : 0;
        const int k0 = (tt - part * NKT) * BK;
        const float* Arow = part ? Arow1 : Arow0;
        const float* Bw = part ? B1 : B0;
#pragma unroll
        for (int q = 0; q < 4; q++) {
            const int k = k0 + q * 4;
            if (k + 4 <= Hh) {
                float4 v = *reinterpret_cast<const float4*>(Arow + k);
                a_reg[q*4+0]=v.x; a_reg[q*4+1]=v.y; a_reg[q*4+2]=v.z; a_reg[q*4+3]=v.w;
            } else {
#pragma unroll
                for (int i = 0; i < 4; i++) a_reg[q*4+i] = (k + i < Hh) ? Arow[k + i] : 0.f;
            }
        }
        const int brow = k0 + brw;
        const bool rok = brow < Hh;
        const float* Bp = Bw + (size_t)brow * Ncols;
#pragma unroll
        for (int q = 0; q < 4; q++) {
            const int cb = bn + bc0 + q * 4;
            if (rok && cb + 4 <= Ncols) {
                float4 v = *reinterpret_cast<const float4*>(Bp + cb);
                b_reg[q*4+0]=v.x; b_reg[q*4+1]=v.y; b_reg[q*4+2]=v.z; b_reg[q*4+3]=v.w;
            } else {
#pragma unroll
                for (int i = 0; i < 4; i++)
                    b_reg[q*4+i] = (rok && cb + i < Ncols) ? Bp[cb + i] : 0.f;
            }
        }
    };
    auto store_tile = [&](int buf) {
        float* ap = &As[buf][tid * ASTRIDE];
#pragma unroll
        for (int i = 0; i < 16; i++) ap[i] = tf32r(a_reg[i]);
        float* bp = &Bs[buf][brw * BSTRIDE + bc0];
#pragma unroll
        for (int i = 0; i < 16; i++) bp[i] = tf32r(b_reg[i]);
    };

    load_tile(0);
    store_tile(0);
    __syncthreads();

    for (int tt = 0; tt < ntiles; tt++) {
        const int buf = tt & 1;
        const bool more = (tt + 1 < ntiles);
        if (more) load_tile(tt + 1);
        const float* Asb = As[buf];
        const float* Bsb = Bs[buf];
#pragma unroll
        for (int kk = 0; kk < 2; kk++) {
            const int k8 = kk * 8;
            float fa0[4], fa1[4], fa2[4], fa3[4];
#pragma unroll
            for (int mt = 0; mt < 4; mt++) {
                const int r = am0 + mt * 16 + g;
                fa0[mt] = Asb[r * ASTRIDE + k8 + tig];
                fa1[mt] = Asb[(r + 8) * ASTRIDE + k8 + tig];
                fa2[mt] = Asb[r * ASTRIDE + k8 + tig + 4];
                fa3[mt] = Asb[(r + 8) * ASTRIDE + k8 + tig + 4];
            }
            float fb0[8], fb1[8];
#pragma unroll
            for (int nt = 0; nt < 8; nt++) {
                const int cn = bn0 + nt * 8 + g;
                fb0[nt] = Bsb[(k8 + tig) * BSTRIDE + cn];
                fb1[nt] = Bsb[(k8 + tig + 4) * BSTRIDE + cn];
            }
#pragma unroll
            for (int mt = 0; mt < 4; mt++)
#pragma unroll
                for (int nt = 0; nt < 8; nt++)
                    mma_tf32(acc[mt][nt], fa0[mt], fa1[mt], fa2[mt], fa3[mt],
                             fb0[nt], fb1[nt]);
        }
        if (more) store_tile(buf ^ 1);
        __syncthreads();
    }

#pragma unroll
    for (int mt = 0; mt < 4; mt++) {
        const int row0 = bm + am0 + mt * 16 + g;
#pragma unroll
        for (int nt = 0; nt < 8; nt++) {
            const int col = bn + bn0 + nt * 8 + 2 * tig;
            if (col < Ncols) {
                float bia = 0.f, bib = 0.f;
                if (bias0) { bia = bias0[col]; bib = bias0[col + 1]; }
                if (bias1) { bia += bias1[col]; bib += bias1[col + 1]; }
                float v0 = acc[mt][nt][0] + bia;
                float v1 = acc[mt][nt][1] + bib;
                float v2 = acc[mt][nt][2] + bia;
                float v3 = acc[mt][nt][3] + bib;
                if (act) {
                    v0 = fmaxf(v0, 0.f); v1 = fmaxf(v1, 0.f);
                    v2 = fmaxf(v2, 0.f); v3 = fmaxf(v3, 0.f);
                }
                *reinterpret_cast<float2*>(&C[(size_t)row0 * Ncols + col]) =
                    make_float2(v0, v1);
                *reinterpret_cast<float2*>(&C[(size_t)(row0 + 8) * Ncols + col]) =
                    make_float2(v2, v3);
            }
        }
    }
}

// ---------------- GAT attention scores ----------------
__global__ void gat_scores_k(const float* __restrict__ al, const float* __restrict__ ar) {
    int w = (blockIdx.x * blockDim.x + threadIdx.x) >> 5;
    int lane = threadIdx.x & 31;
    if (w >= Nn * NHEADS) return;
    int n = w / NHEADS, hd = w % NHEADS;
    const float* zr = g_z + (size_t)n * (NHEADS * Hh) + hd * Hh;
    float sl = 0.f, sr = 0.f;
    for (int c = lane; c < Hh; c += 32) {
        float zv = zr[c];
        sl = fmaf(zv, al[hd * Hh + c], sl);
        sr = fmaf(zv, ar[hd * Hh + c], sr);
    }
#pragma unroll
    for (int o = 16; o; o >>= 1) {
        sl += __shfl_xor_sync(0xFFFFFFFFu, sl, o);
        sr += __shfl_xor_sync(0xFFFFFFFFu, sr, o);
    }
    if (lane == 0) { g_el[w] = sl; g_er[w] = sr; }
}

// ---------------- fused GAT aggregate + relu + head-mean + elu + readout + segsum ----------------
__global__ __launch_bounds__(256) void gat_final_k(
    const int* __restrict__ nbr, const int* __restrict__ gid,
    const float* __restrict__ Wr, const float* __restrict__ br,
    float* __restrict__ out)
{
    int n = blockIdx.x;
    int tid = threadIdx.x;
    __shared__ float alpha[NHEADS][Dd];
    __shared__ int nb[Dd];
    __shared__ float red[256];

    if (tid < Dd) nb[tid] = nbr[n * Dd + tid];
    __syncthreads();

    if (tid < NHEADS * Dd) {
        int hd = tid / Dd, d = tid % Dd;
        float e = g_el[nb[d] * NHEADS + hd] + g_er[n * NHEADS + hd];
        alpha[hd][d] = (e > 0.f) ? e : 0.2f * e;
    }
    __syncthreads();
    if (tid < NHEADS) {
        float mx = -1e30f;
#pragma unroll
        for (int d = 0; d < Dd; d++) mx = fmaxf(mx, alpha[tid][d]);
        float ex[Dd]; float s = 0.f;
#pragma unroll
        for (int d = 0; d < Dd; d++) { ex[d] = expf(alpha[tid][d] - mx); s += ex[d]; }
        float inv = 1.f / s;
#pragma unroll
        for (int d = 0; d < Dd; d++) alpha[tid][d] = ex[d] * inv;
    }
    __syncthreads();

    float accum = 0.f;
    for (int c = tid; c < Hh; c += 256) {
        float mean = 0.f;
#pragma unroll
        for (int hd = 0; hd < NHEADS; hd++) {
            float s = 0.f;
#pragma unroll
            for (int d = 0; d < Dd; d++)
                s = fmaf(alpha[hd][d],
                         g_z[(size_t)nb[d] * (NHEADS * Hh) + hd * Hh + c], s);
            mean += fmaxf(s, 0.f);
        }
        mean *= (1.f / NHEADS);
        float e = (mean > 0.f) ? mean : (expf(mean) - 1.f);
        accum = fmaf(e, Wr[c], accum);
    }
    red[tid] = accum;
    __syncthreads();
    for (int s = 128; s > 0; s >>= 1) {
        if (tid < s) red[tid] += red[tid + s];
        __syncthreads();
    }
    if (tid == 0) atomicAdd(&out[gid[n]], red[0] + br[0]);
}

// ---------------- launch ----------------
extern "C" void kernel_launch(void* const* d_in, const int* in_sizes, int n_in,
                              void* d_out, int out_size) {
    const int* node_ids  = (const int*)d_in[0];
    const int* neighbors = (const int*)d_in[1];
    const int* graph_ids = (const int*)d_in[2];
    const float* emb = (const float*)d_in[4];
    const float* W[3][7];   // Wih, Whh, bih, bhh, Wself, Wneigh, b
    int p = 5;
    for (int l = 0; l < 3; l++)
        for (int q = 0; q < 7; q++) W[l][q] = (const float*)d_in[p++];
    const float* Wg = (const float*)d_in[p++];
    const float* al = (const float*)d_in[p++];
    const float* ar = (const float*)d_in[p++];
    const float* Wr = (const float*)d_in[p++];
    const float* br = (const float*)d_in[p++];
    float* out = (float*)d_out;

    float *xA, *xB, *hA, *hB, *xw, *z;
    cudaGetSymbolAddress((void**)&xA, g_xA);
    cudaGetSymbolAddress((void**)&xB, g_xB);
    cudaGetSymbolAddress((void**)&hA, g_hA);
    cudaGetSymbolAddress((void**)&hB, g_hB);
    cudaGetSymbolAddress((void**)&xw, g_xw);
    cudaGetSymbolAddress((void**)&z, g_z);

    const int NH = Nn * Hh;
    zero_k<<<1, 64>>>(out, out_size);
    embed_k<<<(NH + 255) / 256, 256>>>(node_ids, emb, xA);

    dim3 gXW(NG / BN + ((NG % BN) ? 1 : 0), (8 * Nn) / BM);   // 16 x 256
    dim3 gHC(NG / BN + ((NG % BN) ? 1 : 0), Nn / BM);         // 16 x 32
    dim3 gFc((Hh + BN - 1) / BN, Nn / BM);                    // 4 x 32
    dim3 gZ((NHEADS * Hh + BN - 1) / BN, Nn / BM);            // 20 x 32

    float* xin = xA;
    float* xout = xB;
    for (int l = 0; l < 3; l++) {
        permute_w_k<<<(Hh * NG + 255) / 256, 256>>>(W[l][0], W[l][1], W[l][2], W[l][3]);
        gemm_xw<<<gXW, 128>>>(xin, neighbors, xw);
        cell0_k<<<(NH + 255) / 256, 256>>>(xw, hA);
        float* hin = hA;
        float* hout = hB;
        for (int t = 1; t < Dd; t++) {
            gemm_hcell<<<gHC, 128>>>(hin, xw + (size_t)t * Nn * NG, hout);
            float* tmp = hin; hin = hout; hout = tmp;
        }
        gemm_mma<<<gFc, 128>>>(xin, nullptr, 0, hin,
                               W[l][4], W[l][5], W[l][6], nullptr,
                               xout, Hh, 1);
        float* tmp = xin; xin = xout; xout = tmp;
    }

    gemm_mma<<<gZ, 128>>>(xin, nullptr, 0, nullptr,
                          Wg, nullptr, nullptr, nullptr,
                          z, NHEADS * Hh, 0);
    gat_scores_k<<<(Nn * NHEADS * 32 + 127) / 128, 128>>>(al, ar);
    gat_final_k<<<Nn, 256>>>(neighbors, graph_ids, Wr, br, out);
}

// round 9
// speedup vs baseline: 1.0552x; 1.0552x over previous
#include <cuda_runtime.h>
#include <stdint.h>
#include <math.h>

#define Nn 4096
#define Hh 500
#define Dd 8
#define NHEADS 5
#define NG 2000

#define BM 128
#define BN 128
#define BK 16
#define ASTRIDE 20    // 16 + 4 pad
#define BSTRIDE 132   // 128 + 4 pad
#define NKT 32        // ceil(500/16)

// ---------------- scratch ----------------
__device__ float g_xA[Nn * Hh];
__device__ float g_xB[Nn * Hh];
__device__ float g_hA[Nn * Hh];
__device__ float g_hB[Nn * Hh];
__device__ float g_c[Nn * Hh];
__device__ float g_wihp[Hh * NG];   // interleaved (col=4j+gate), tf32-rounded
__device__ float g_whhp[Hh * NG];
__device__ float g_bp[NG];
__device__ float g_z[Nn * NHEADS * Hh];
__device__ float g_el[Nn * NHEADS];
__device__ float g_er[Nn * NHEADS];

// ---------------- helpers ----------------
__device__ __forceinline__ float tf32r(float x) {
    unsigned int u;
    asm("cvt.rna.tf32.f32 %0, %1;" : "=r"(u) : "f"(x));
    return __uint_as_float(u);
}
__device__ __forceinline__ float sigm(float x) { return 1.f / (1.f + expf(-x)); }
__device__ __forceinline__ uint32_t s2u(const void* p) {
    uint32_t a;
    asm("{ .reg .u64 t; cvta.to.shared.u64 t, %1; cvt.u32.u64 %0, t; }" : "=r"(a) : "l"(p));
    return a;
}
__device__ __forceinline__ void cpa16(uint32_t s, const void* g, uint32_t nbytes) {
    asm volatile("cp.async.cg.shared.global [%0], [%1], 16, %2;" :: "r"(s), "l"(g), "r"(nbytes));
}
__device__ __forceinline__ void cpa_commit() {
    asm volatile("cp.async.commit_group;" ::: "memory");
}
template <int N>
__device__ __forceinline__ void cpa_wait() {
    asm volatile("cp.async.wait_group %0;" :: "n"(N) : "memory");
}
__device__ __forceinline__ void mma_tf32(float c[4], float a0, float a1, float a2, float a3,
                                         float b0, float b1) {
    asm volatile(
        "mma.sync.aligned.m16n8k8.row.col.f32.tf32.tf32.f32 "
        "{%0,%1,%2,%3}, {%4,%5,%6,%7}, {%8,%9}, {%0,%1,%2,%3};"
        : "+f"(c[0]), "+f"(c[1]), "+f"(c[2]), "+f"(c[3])
        : "r"(__float_as_uint(a0)), "r"(__float_as_uint(a1)),
          "r"(__float_as_uint(a2)), "r"(__float_as_uint(a3)),
          "r"(__float_as_uint(b0)), "r"(__float_as_uint(b1)));
}

// ---------------- utility kernels ----------------
__global__ void zero_k(float* p, int n) {
    int i = blockIdx.x * blockDim.x + threadIdx.x;
    if (i < n) p[i] = 0.f;
}
__global__ void embed_k(const int* __restrict__ ids, const float* __restrict__ emb,
                        float* __restrict__ x) {
    int i = blockIdx.x * blockDim.x + threadIdx.x;
    if (i < Nn * Hh) {
        int n = i / Hh, c = i % Hh;
        x[i] = tf32r(emb[ids[n] * Hh + c]);   // pre-round: staged raw via cp.async
    }
}
// interleave gate columns (col = 4j+gate) + tf32 pre-round; combined bias.
__global__ void permute_w_k(const float* __restrict__ Wih, const float* __restrict__ Whh,
                            const float* __restrict__ bih, const float* __restrict__ bhh) {
    int idx = blockIdx.x * blockDim.x + threadIdx.x;
    if (idx >= Hh * NG) return;
    int k = idx / NG, cidx = idx % NG;
    int gate = cidx & 3, j = cidx >> 2;
    int src = k * NG + gate * Hh + j;
    g_wihp[idx] = tf32r(Wih[src]);
    g_whhp[idx] = tf32r(Whh[src]);
    if (k == 0) g_bp[cidx] = bih[gate * Hh + j] + bhh[gate * Hh + j];
}

// ---------------- gates GEMM + fused LSTM cell (mma.sync tf32, cp.async staging) ----------------
// gates[128,128-slice] = [x_nbr | h] @ [Wihp; Whhp] (+bias), interleaved cols -> cell -> Hout, g_c
__global__ __launch_bounds__(128) void gates_cell_k(
    const float* __restrict__ X, const float* __restrict__ Hin,
    const int* __restrict__ nbr, int t, int first,
    float* __restrict__ Hout)
{
    __shared__ float As[2][BM * ASTRIDE];
    __shared__ float Bs[2][BK * BSTRIDE];

    const int tid = threadIdx.x;
    const int bm = blockIdx.y * BM;
    const int bn = blockIdx.x * BN;
    const int lane = tid & 31;
    const int warp = tid >> 5;
    const int g = lane >> 2, tig = lane & 3;
    const int am0 = (warp >> 1) * 64;
    const int bn0 = (warp & 1) * 64;
    const int brw = tid >> 3;               // B row 0..15
    const int bc0 = (tid & 7) * 16;         // B col chunk base

    const float* Arow0 = X + (size_t)nbr[(bm + tid) * Dd + t] * Hh;
    const float* Arow1 = Hin + (size_t)(bm + tid) * Hh;
    const int ntiles = first ? NKT : 2 * NKT;

    const uint32_t asm0 = s2u(&As[0][0]);
    const uint32_t bsm0 = s2u(&Bs[0][0]);

    float acc[4][8][4];
#pragma unroll
    for (int mt = 0; mt < 4; mt++)
#pragma unroll
        for (int nt = 0; nt < 8; nt++)
#pragma unroll
            for (int r = 0; r < 4; r++) acc[mt][nt][r] = 0.f;

    auto issue_tile = [&](int tt, int buf) {
        const int part = (tt >= NKT) ? 1 : 0;
        const int k0 = (tt - part * NKT) * BK;
        const float* Arow = part ? Arow1 : Arow0;
        const float* Bw = part ? g_whhp : g_wihp;
        const uint32_t ab = asm0 + buf * (BM * ASTRIDE * 4) + tid * (ASTRIDE * 4);
#pragma unroll
        for (int q = 0; q < 4; q++) {
            const int k = k0 + q * 4;
            cpa16(ab + q * 16, Arow + k, (k < Hh) ? 16u : 0u);
        }
        const int brow = k0 + brw;
        const bool rok = brow < Hh;
        const float* Bp = Bw + (size_t)brow * NG;
        const uint32_t bb = bsm0 + buf * (BK * BSTRIDE * 4) + brw * (BSTRIDE * 4) + bc0 * 4;
#pragma unroll
        for (int q = 0; q < 4; q++) {
            const int cb = bn + bc0 + q * 4;
            cpa16(bb + q * 16, Bp + ((rok && cb < NG) ? cb : 0),
                  (rok && cb < NG) ? 16u : 0u);
        }
        cpa_commit();
    };

    issue_tile(0, 0);

    for (int tt = 0; tt < ntiles; tt++) {
        const int buf = tt & 1;
        const bool more = (tt + 1 < ntiles);
        if (more) { issue_tile(tt + 1, buf ^ 1); cpa_wait<1>(); }
        else cpa_wait<0>();
        __syncthreads();

        const float* Asb = As[buf];
        const float* Bsb = Bs[buf];
#pragma unroll
        for (int kk = 0; kk < 2; kk++) {
            const int k8 = kk * 8;
            float fa0[4], fa1[4], fa2[4], fa3[4];
#pragma unroll
            for (int mt = 0; mt < 4; mt++) {
                const int r = am0 + mt * 16 + g;
                fa0[mt] = Asb[r * ASTRIDE + k8 + tig];
                fa1[mt] = Asb[(r + 8) * ASTRIDE + k8 + tig];
                fa2[mt] = Asb[r * ASTRIDE + k8 + tig + 4];
                fa3[mt] = Asb[(r + 8) * ASTRIDE + k8 + tig + 4];
            }
            float fb0[8], fb1[8];
#pragma unroll
            for (int nt = 0; nt < 8; nt++) {
                const int cn = bn0 + nt * 8 + g;
                fb0[nt] = Bsb[(k8 + tig) * BSTRIDE + cn];
                fb1[nt] = Bsb[(k8 + tig + 4) * BSTRIDE + cn];
            }
#pragma unroll
            for (int mt = 0; mt < 4; mt++)
#pragma unroll
                for (int nt = 0; nt < 8; nt++)
                    mma_tf32(acc[mt][nt], fa0[mt], fa1[mt], fa2[mt], fa3[mt],
                             fb0[nt], fb1[nt]);
        }
        __syncthreads();
    }

    // ---- fused LSTM cell epilogue ----
    // cols interleaved 4j+gate: tig-even thread holds (i,f); lane^1 holds (g,o).
#pragma unroll
    for (int mt = 0; mt < 4; mt++) {
        const int row0 = bm + am0 + mt * 16 + g;
#pragma unroll
        for (int nt = 0; nt < 8; nt++) {
            const int col = bn + bn0 + nt * 8 + 2 * tig;
            const bool ok = col < NG;
            float v0 = 0.f, v1 = 0.f, v2 = 0.f, v3 = 0.f;
            if (ok) {
                const float2 bi = *reinterpret_cast<const float2*>(&g_bp[col]);
                v0 = acc[mt][nt][0] + bi.x;
                v1 = acc[mt][nt][1] + bi.y;
                v2 = acc[mt][nt][2] + bi.x;
                v3 = acc[mt][nt][3] + bi.y;
            }
            float gg0 = __shfl_xor_sync(0xFFFFFFFFu, v0, 1);
            float oo0 = __shfl_xor_sync(0xFFFFFFFFu, v1, 1);
            float gg1 = __shfl_xor_sync(0xFFFFFFFFu, v2, 1);
            float oo1 = __shfl_xor_sync(0xFFFFFFFFu, v3, 1);
            if (ok && (tig & 1) == 0) {
                const int j = col >> 2;
                {
                    float cp = first ? 0.f : g_c[(size_t)row0 * Hh + j];
                    float c = sigm(v1) * cp + sigm(v0) * tanhf(gg0);
                    g_c[(size_t)row0 * Hh + j] = c;
                    Hout[(size_t)row0 * Hh + j] = tf32r(sigm(oo0) * tanhf(c));
                }
                {
                    const int r1 = row0 + 8;
                    float cp = first ? 0.f : g_c[(size_t)r1 * Hh + j];
                    float c = sigm(v3) * cp + sigm(v2) * tanhf(gg1);
                    g_c[(size_t)r1 * Hh + j] = c;
                    Hout[(size_t)r1 * Hh + j] = tf32r(sigm(oo1) * tanhf(c));
                }
            }
        }
    }
}

// ---------------- mma.sync GEMM (fc + GAT z), round-6 proven ----------------
__global__ __launch_bounds__(128, 2) void gemm_mma(
    const float* __restrict__ X0, const int* __restrict__ nbr, int t,
    const float* __restrict__ X1,
    const float* __restrict__ B0, const float* __restrict__ B1,
    const float* __restrict__ bias0, const float* __restrict__ bias1,
    float* __restrict__ C, int Ncols, int act)
{
    __shared__ float As[2][BM * ASTRIDE];
    __shared__ float Bs[2][BK * BSTRIDE];

    const int tid = threadIdx.x;
    const int bm = blockIdx.y * BM;
    const int bn = blockIdx.x * BN;
    const int lane = tid & 31;
    const int warp = tid >> 5;
    const int g = lane >> 2, tig = lane & 3;
    const int am0 = (warp >> 1) * 64;
    const int bn0 = (warp & 1) * 64;
    const int brw = tid >> 3;
    const int bc0 = (tid & 7) * 16;

    const int arow0 = nbr ? nbr[(bm + tid) * Dd + t] : (bm + tid);
    const float* Arow0 = X0 + (size_t)arow0 * Hh;
    const float* Arow1 = X1 ? (X1 + (size_t)(bm + tid) * Hh) : nullptr;
    const int ntiles = (X1 ? 2 : 1) * NKT;

    float acc[4][8][4];
#pragma unroll
    for (int mt = 0; mt < 4; mt++)
#pragma unroll
        for (int nt = 0; nt < 8; nt++)
#pragma unroll
            for (int r = 0; r < 4; r++) acc[mt][nt][r] = 0.f;

    float a_reg[16], b_reg[16];

    auto load_tile = [&](int tt) {
        const int part = (tt >= NKT) ? 1 : 0;
        const int k0 = (tt - part * NKT) * BK;
        const float* Arow = part ? Arow1 : Arow0;
        const float* Bw = part ? B1 : B0;
#pragma unroll
        for (int q = 0; q < 4; q++) {
            const int k = k0 + q * 4;
            if (k + 4 <= Hh) {
                float4 v = *reinterpret_cast<const float4*>(Arow + k);
                a_reg[q*4+0]=v.x; a_reg[q*4+1]=v.y; a_reg[q*4+2]=v.z; a_reg[q*4+3]=v.w;
            } else {
#pragma unroll
                for (int i = 0; i < 4; i++) a_reg[q*4+i] = (k + i < Hh) ? Arow[k + i] : 0.f;
            }
        }
        const int brow = k0 + brw;
        const bool rok = brow < Hh;
        const float* Bp = Bw + (size_t)brow * Ncols;
#pragma unroll
        for (int q = 0; q < 4; q++) {
            const int cb = bn + bc0 + q * 4;
            if (rok && cb + 4 <= Ncols) {
                float4 v = *reinterpret_cast<const float4*>(Bp + cb);
                b_reg[q*4+0]=v.x; b_reg[q*4+1]=v.y; b_reg[q*4+2]=v.z; b_reg[q*4+3]=v.w;
            } else {
#pragma unroll
                for (int i = 0; i < 4; i++)
                    b_reg[q*4+i] = (rok && cb + i < Ncols) ? Bp[cb + i] : 0.f;
            }
        }
    };
    auto store_tile = [&](int buf) {
        float* ap = &As[buf][tid * ASTRIDE];
#pragma unroll
        for (int i = 0; i < 16; i++) ap[i] = tf32r(a_reg[i]);
        float* bp = &Bs[buf][brw * BSTRIDE + bc0];
#pragma unroll
        for (int i = 0; i < 16; i++) bp[i] = tf32r(b_reg[i]);
    };

    load_tile(0);
    store_tile(0);
    __syncthreads();

    for (int tt = 0; tt < ntiles; tt++) {
        const int buf = tt & 1;
        const bool more = (tt + 1 < ntiles);
        if (more) load_tile(tt + 1);
        const float* Asb = As[buf];
        const float* Bsb = Bs[buf];
#pragma unroll
        for (int kk = 0; kk < 2; kk++) {
            const int k8 = kk * 8;
            float fa0[4], fa1[4], fa2[4], fa3[4];
#pragma unroll
            for (int mt = 0; mt < 4; mt++) {
                const int r = am0 + mt * 16 + g;
                fa0[mt] = Asb[r * ASTRIDE + k8 + tig];
                fa1[mt] = Asb[(r + 8) * ASTRIDE + k8 + tig];
                fa2[mt] = Asb[r * ASTRIDE + k8 + tig + 4];
                fa3[mt] = Asb[(r + 8) * ASTRIDE + k8 + tig + 4];
            }
            float fb0[8], fb1[8];
#pragma unroll
            for (int nt = 0; nt < 8; nt++) {
                const int cn = bn0 + nt * 8 + g;
                fb0[nt] = Bsb[(k8 + tig) * BSTRIDE + cn];
                fb1[nt] = Bsb[(k8 + tig + 4) * BSTRIDE + cn];
            }
#pragma unroll
            for (int mt = 0; mt < 4; mt++)
#pragma unroll
                for (int nt = 0; nt < 8; nt++)
                    mma_tf32(acc[mt][nt], fa0[mt], fa1[mt], fa2[mt], fa3[mt],
                             fb0[nt], fb1[nt]);
        }
        if (more) store_tile(buf ^ 1);
        __syncthreads();
    }

#pragma unroll
    for (int mt = 0; mt < 4; mt++) {
        const int row0 = bm + am0 + mt * 16 + g;
#pragma unroll
        for (int nt = 0; nt < 8; nt++) {
            const int col = bn + bn0 + nt * 8 + 2 * tig;
            if (col < Ncols) {
                float bia = 0.f, bib = 0.f;
                if (bias0) { bia = bias0[col]; bib = bias0[col + 1]; }
                if (bias1) { bia += bias1[col]; bib += bias1[col + 1]; }
                float v0 = acc[mt][nt][0] + bia;
                float v1 = acc[mt][nt][1] + bib;
                float v2 = acc[mt][nt][2] + bia;
                float v3 = acc[mt][nt][3] + bib;
                if (act) {   // feeds next-layer gates (raw cp.async staging): relu + tf32 round
                    v0 = tf32r(fmaxf(v0, 0.f)); v1 = tf32r(fmaxf(v1, 0.f));
                    v2 = tf32r(fmaxf(v2, 0.f)); v3 = tf32r(fmaxf(v3, 0.f));
                }
                *reinterpret_cast<float2*>(&C[(size_t)row0 * Ncols + col]) = make_float2(v0, v1);
                *reinterpret_cast<float2*>(&C[(size_t)(row0 + 8) * Ncols + col]) = make_float2(v2, v3);
            }
        }
    }
}

// ---------------- GAT attention scores ----------------
__global__ void gat_scores_k(const float* __restrict__ al, const float* __restrict__ ar) {
    int w = (blockIdx.x * blockDim.x + threadIdx.x) >> 5;
    int lane = threadIdx.x & 31;
    if (w >= Nn * NHEADS) return;
    int n = w / NHEADS, hd = w % NHEADS;
    const float* zr = g_z + (size_t)n * (NHEADS * Hh) + hd * Hh;
    float sl = 0.f, sr = 0.f;
    for (int c = lane; c < Hh; c += 32) {
        float zv = zr[c];
        sl = fmaf(zv, al[hd * Hh + c], sl);
        sr = fmaf(zv, ar[hd * Hh + c], sr);
    }
#pragma unroll
    for (int o = 16; o; o >>= 1) {
        sl += __shfl_xor_sync(0xFFFFFFFFu, sl, o);
        sr += __shfl_xor_sync(0xFFFFFFFFu, sr, o);
    }
    if (lane == 0) { g_el[w] = sl; g_er[w] = sr; }
}

// ---------------- fused GAT aggregate + relu + head-mean + elu + readout + segsum ----------------
__global__ __launch_bounds__(256) void gat_final_k(
    const int* __restrict__ nbr, const int* __restrict__ gid,
    const float* __restrict__ Wr, const float* __restrict__ br,
    float* __restrict__ out)
{
    int n = blockIdx.x;
    int tid = threadIdx.x;
    __shared__ float alpha[NHEADS][Dd];
    __shared__ int nb[Dd];
    __shared__ float red[256];

    if (tid < Dd) nb[tid] = nbr[n * Dd + tid];
    __syncthreads();

    if (tid < NHEADS * Dd) {
        int hd = tid / Dd, d = tid % Dd;
        float e = g_el[nb[d] * NHEADS + hd] + g_er[n * NHEADS + hd];
        alpha[hd][d] = (e > 0.f) ? e : 0.2f * e;
    }
    __syncthreads();
    if (tid < NHEADS) {
        float mx = -1e30f;
#pragma unroll
        for (int d = 0; d < Dd; d++) mx = fmaxf(mx, alpha[tid][d]);
        float ex[Dd]; float s = 0.f;
#pragma unroll
        for (int d = 0; d < Dd; d++) { ex[d] = expf(alpha[tid][d] - mx); s += ex[d]; }
        float inv = 1.f / s;
#pragma unroll
        for (int d = 0; d < Dd; d++) alpha[tid][d] = ex[d] * inv;
    }
    __syncthreads();

    float accum = 0.f;
    for (int c = tid; c < Hh; c += 256) {
        float mean = 0.f;
#pragma unroll
        for (int hd = 0; hd < NHEADS; hd++) {
            float s = 0.f;
#pragma unroll
            for (int d = 0; d < Dd; d++)
                s = fmaf(alpha[hd][d],
                         g_z[(size_t)nb[d] * (NHEADS * Hh) + hd * Hh + c], s);
            mean += fmaxf(s, 0.f);
        }
        mean *= (1.f / NHEADS);
        float e = (mean > 0.f) ? mean : (expf(mean) - 1.f);
        accum = fmaf(e, Wr[c], accum);
    }
    red[tid] = accum;
    __syncthreads();
    for (int s = 128; s > 0; s >>= 1) {
        if (tid < s) red[tid] += red[tid + s];
        __syncthreads();
    }
    if (tid == 0) atomicAdd(&out[gid[n]], red[0] + br[0]);
}

// ---------------- launch ----------------
extern "C" void kernel_launch(void* const* d_in, const int* in_sizes, int n_in,
                              void* d_out, int out_size) {
    const int* node_ids  = (const int*)d_in[0];
    const int* neighbors = (const int*)d_in[1];
    const int* graph_ids = (const int*)d_in[2];
    const float* emb = (const float*)d_in[4];
    const float* W[3][7];
    int p = 5;
    for (int l = 0; l < 3; l++)
        for (int q = 0; q < 7; q++) W[l][q] = (const float*)d_in[p++];
    const float* Wg = (const float*)d_in[p++];
    const float* al = (const float*)d_in[p++];
    const float* ar = (const float*)d_in[p++];
    const float* Wr = (const float*)d_in[p++];
    const float* br = (const float*)d_in[p++];
    float* out = (float*)d_out;

    float *xA, *xB, *hA, *hB, *z;
    cudaGetSymbolAddress((void**)&xA, g_xA);
    cudaGetSymbolAddress((void**)&xB, g_xB);
    cudaGetSymbolAddress((void**)&hA, g_hA);
    cudaGetSymbolAddress((void**)&hB, g_hB);
    cudaGetSymbolAddress((void**)&z, g_z);

    const int NH = Nn * Hh;
    zero_k<<<1, 64>>>(out, out_size);
    embed_k<<<(NH + 255) / 256, 256>>>(node_ids, emb, xA);

    dim3 gGates((NG + BN - 1) / BN, Nn / BM);          // 16 x 32
    dim3 gFc((Hh + BN - 1) / BN, Nn / BM);             // 4 x 32
    dim3 gZ((NHEADS * Hh + BN - 1) / BN, Nn / BM);     // 20 x 32

    float* xin = xA;
    float* xout = xB;
    for (int l = 0; l < 3; l++) {
        permute_w_k<<<(Hh * NG + 255) / 256, 256>>>(W[l][0], W[l][1], W[l][2], W[l][3]);
        float* hin = hA;
        float* hout = hB;
        for (int t = 0; t < Dd; t++) {
            gates_cell_k<<<gGates, 128>>>(xin, hin, neighbors, t, t == 0 ? 1 : 0, hout);
            float* tmp = hin; hin = hout; hout = tmp;
        }
        gemm_mma<<<gFc, 128>>>(xin, nullptr, 0, hin,
                               W[l][4], W[l][5], W[l][6], nullptr,
                               xout, Hh, 1);
        float* tmp = xin; xin = xout; xout = tmp;
    }

    gemm_mma<<<gZ, 128>>>(xin, nullptr, 0, nullptr,
                          Wg, nullptr, nullptr, nullptr,
                          z, NHEADS * Hh, 0);
    gat_scores_k<<<(Nn * NHEADS * 32 + 127) / 128, 128>>>(al, ar);
    gat_final_k<<<Nn, 256>>>(neighbors, graph_ids, Wr, br, out);
}

// round 10
// speedup vs baseline: 1.5507x; 1.4696x over previous
#include <cuda_runtime.h>
#include <cuda_fp16.h>
#include <stdint.h>
#include <math.h>

#define Nn 4096
#define Hh 500
#define Dd 8
#define NHEADS 5
#define NG 2000
#define KP 512          // padded K per part (halfs)
#define NPG 2048        // padded gates N
#define NPF 512         // padded fc N
#define NPZ 2560        // padded z N
#define NZ 2500

#define BM 128
#define AW 20           // uint32 words per smem row (40 halfs = 80B, conflict-free)

// ---------------- scratch ----------------
__device__ __half g_x16A[(size_t)Nn * KP];
__device__ __half g_x16B[(size_t)Nn * KP];
__device__ __half g_h16A[(size_t)Nn * KP];
__device__ __half g_h16B[(size_t)Nn * KP];
__device__ float  g_c[(size_t)Nn * Hh];
__device__ __half g_wg[(size_t)NPG * 1024];
__device__ __half g_wfc[(size_t)NPF * 1024];
__device__ __half g_wz[(size_t)NPZ * 512];
__device__ float  g_bpg[NPG];
__device__ float  g_bfc[NPF];
__device__ float  g_z[(size_t)Nn * NZ];
__device__ float  g_el[Nn * NHEADS];
__device__ float  g_er[Nn * NHEADS];

// ---------------- helpers ----------------
__device__ __forceinline__ float sigm(float x) { return 1.f / (1.f + expf(-x)); }
__device__ __forceinline__ uint32_t s2u(const void* p) {
    uint32_t a;
    asm("{ .reg .u64 t; cvta.to.shared.u64 t, %1; cvt.u32.u64 %0, t; }" : "=r"(a) : "l"(p));
    return a;
}
__device__ __forceinline__ void cpa16(uint32_t s, const void* g) {
    asm volatile("cp.async.cg.shared.global [%0], [%1], 16;" :: "r"(s), "l"(g));
}
__device__ __forceinline__ void cpa_commit() {
    asm volatile("cp.async.commit_group;" ::: "memory");
}
template <int N>
__device__ __forceinline__ void cpa_wait() {
    asm volatile("cp.async.wait_group %0;" :: "n"(N) : "memory");
}
__device__ __forceinline__ void mma16(float c[4], const uint32_t a[4], const uint32_t b[2]) {
    asm volatile(
        "mma.sync.aligned.m16n8k16.row.col.f32.f16.f16.f32 "
        "{%0,%1,%2,%3}, {%4,%5,%6,%7}, {%8,%9}, {%0,%1,%2,%3};"
        : "+f"(c[0]), "+f"(c[1]), "+f"(c[2]), "+f"(c[3])
        : "r"(a[0]), "r"(a[1]), "r"(a[2]), "r"(a[3]), "r"(b[0]), "r"(b[1]));
}

// ---------------- utility kernels ----------------
__global__ void zero_k(float* p, int n) {
    int i = blockIdx.x * blockDim.x + threadIdx.x;
    if (i < n) p[i] = 0.f;
}
__global__ void embed16_k(const int* __restrict__ ids, const float* __restrict__ emb) {
    int i = blockIdx.x * blockDim.x + threadIdx.x;
    if (i < Nn * KP) {
        int n = i >> 9, j = i & 511;
        g_x16A[i] = __float2half(j < Hh ? emb[(size_t)ids[n] * Hh + j] : 0.f);
    }
}
__global__ void build_wg_k(const float* __restrict__ Wih, const float* __restrict__ Whh,
                           const float* __restrict__ bih, const float* __restrict__ bhh) {
    int idx = blockIdx.x * blockDim.x + threadIdx.x;
    if (idx >= NPG * 1024) return;
    int n = idx >> 10, k = idx & 1023;
    float v = 0.f;
    if (n < NG) {
        int gate = n & 3, j = n >> 2, scol = gate * Hh + j;
        if (k < 512) { if (k < Hh) v = Wih[(size_t)k * NG + scol]; }
        else { int kk = k - 512; if (kk < Hh) v = Whh[(size_t)kk * NG + scol]; }
        if (k == 0) g_bpg[n] = bih[scol] + bhh[scol];
    } else if (k == 0) g_bpg[n] = 0.f;
    g_wg[idx] = __float2half(v);
}
__global__ void build_wfc_k(const float* __restrict__ Wself, const float* __restrict__ Wneigh,
                            const float* __restrict__ b) {
    int idx = blockIdx.x * blockDim.x + threadIdx.x;
    if (idx >= NPF * 1024) return;
    int n = idx >> 10, k = idx & 1023;
    float v = 0.f;
    if (n < Hh) {
        if (k < 512) { if (k < Hh) v = Wself[(size_t)k * Hh + n]; }
        else { int kk = k - 512; if (kk < Hh) v = Wneigh[(size_t)kk * Hh + n]; }
        if (k == 0) g_bfc[n] = b[n];
    } else if (k == 0) g_bfc[n] = 0.f;
    g_wfc[idx] = __float2half(v);
}
__global__ void build_wz_k(const float* __restrict__ Wg) {
    int idx = blockIdx.x * blockDim.x + threadIdx.x;
    if (idx >= NPZ * 512) return;
    int n = idx >> 9, k = idx & 511;
    float v = 0.f;
    if (n < NZ && k < Hh) v = Wg[(size_t)k * NZ + n];
    g_wz[idx] = __float2half(v);
}

// ---------------- gates GEMM (fp16 mma) + fused LSTM cell ----------------
__global__ __launch_bounds__(128) void gates16_cell_k(
    const __half* __restrict__ X, const __half* __restrict__ Hin,
    const int* __restrict__ nbr, int t, int first, __half* __restrict__ Hout)
{
    __shared__ uint32_t Asu[2][BM * AW];
    __shared__ uint32_t Bsu[2][BM * AW];
    const int tid = threadIdx.x;
    const int bm = blockIdx.y * BM;
    const int bn = blockIdx.x * BM;
    const int lane = tid & 31, warp = tid >> 5;
    const int g = lane >> 2, tig = lane & 3;
    const int am0 = (warp >> 1) * 64, bn0 = (warp & 1) * 64;

    const __half* a0 = X + (size_t)nbr[(bm + tid) * Dd + t] * KP;
    const __half* a1 = Hin + (size_t)(bm + tid) * KP;
    const __half* wr = g_wg + (size_t)(bn + tid) * 1024;
    const int ntiles = first ? 16 : 32;

    const uint32_t abase = s2u(&Asu[0][0]);
    const uint32_t bbase = s2u(&Bsu[0][0]);

    float acc[4][8][4];
#pragma unroll
    for (int mt = 0; mt < 4; mt++)
#pragma unroll
        for (int nt = 0; nt < 8; nt++)
#pragma unroll
            for (int r = 0; r < 4; r++) acc[mt][nt][r] = 0.f;

    auto issue = [&](int tt, int buf) {
        const __half* src = (tt < 16) ? (a0 + tt * 32) : (a1 + (tt - 16) * 32);
        const uint32_t ad = abase + buf * (BM * AW * 4) + tid * (AW * 4);
#pragma unroll
        for (int q = 0; q < 4; q++) cpa16(ad + q * 16, src + q * 8);
        const __half* ws = wr + tt * 32;
        const uint32_t bd = bbase + buf * (BM * AW * 4) + tid * (AW * 4);
#pragma unroll
        for (int q = 0; q < 4; q++) cpa16(bd + q * 16, ws + q * 8);
        cpa_commit();
    };

    issue(0, 0);
    for (int tt = 0; tt < ntiles; tt++) {
        const int buf = tt & 1;
        const bool more = tt + 1 < ntiles;
        if (more) { issue(tt + 1, buf ^ 1); cpa_wait<1>(); } else cpa_wait<0>();
        __syncthreads();
        const uint32_t* Au = Asu[buf];
        const uint32_t* Bu = Bsu[buf];
#pragma unroll
        for (int s = 0; s < 2; s++) {
            const int wb = s * 8;
            uint32_t fa[4][4], fb[8][2];
#pragma unroll
            for (int mt = 0; mt < 4; mt++) {
                const int r = am0 + mt * 16 + g;
                fa[mt][0] = Au[r * AW + wb + tig];
                fa[mt][1] = Au[(r + 8) * AW + wb + tig];
                fa[mt][2] = Au[r * AW + wb + tig + 4];
                fa[mt][3] = Au[(r + 8) * AW + wb + tig + 4];
            }
#pragma unroll
            for (int nt = 0; nt < 8; nt++) {
                const int cn = bn0 + nt * 8 + g;
                fb[nt][0] = Bu[cn * AW + wb + tig];
                fb[nt][1] = Bu[cn * AW + wb + tig + 4];
            }
#pragma unroll
            for (int mt = 0; mt < 4; mt++)
#pragma unroll
                for (int nt = 0; nt < 8; nt++)
                    mma16(acc[mt][nt], fa[mt], fb[nt]);
        }
        __syncthreads();
    }

    // fused LSTM cell epilogue: cols interleaved 4j+gate.
#pragma unroll
    for (int mt = 0; mt < 4; mt++) {
        const int row0 = bm + am0 + mt * 16 + g;
#pragma unroll
        for (int nt = 0; nt < 8; nt++) {
            const int col = bn + bn0 + nt * 8 + 2 * tig;
            const bool ok = col < NG;
            float v0 = 0.f, v1 = 0.f, v2 = 0.f, v3 = 0.f;
            if (ok) {
                const float2 bi = *reinterpret_cast<const float2*>(&g_bpg[col]);
                v0 = acc[mt][nt][0] + bi.x;
                v1 = acc[mt][nt][1] + bi.y;
                v2 = acc[mt][nt][2] + bi.x;
                v3 = acc[mt][nt][3] + bi.y;
            }
            float gg0 = __shfl_xor_sync(0xFFFFFFFFu, v0, 1);
            float oo0 = __shfl_xor_sync(0xFFFFFFFFu, v1, 1);
            float gg1 = __shfl_xor_sync(0xFFFFFFFFu, v2, 1);
            float oo1 = __shfl_xor_sync(0xFFFFFFFFu, v3, 1);
            if (ok && (tig & 1) == 0) {
                const int j = col >> 2;
                {
                    float cp = first ? 0.f : g_c[(size_t)row0 * Hh + j];
                    float c = sigm(v1) * cp + sigm(v0) * tanhf(gg0);
                    g_c[(size_t)row0 * Hh + j] = c;
                    Hout[(size_t)row0 * KP + j] = __float2half(sigm(oo0) * tanhf(c));
                }
                {
                    const int r1 = row0 + 8;
                    float cp = first ? 0.f : g_c[(size_t)r1 * Hh + j];
                    float c = sigm(v3) * cp + sigm(v2) * tanhf(gg1);
                    g_c[(size_t)r1 * Hh + j] = c;
                    Hout[(size_t)r1 * KP + j] = __float2half(sigm(oo1) * tanhf(c));
                }
            }
        }
    }
}

// ---------------- generic fp16 GEMM (fc / z) ----------------
__global__ __launch_bounds__(128) void gemm16_k(
    const __half* __restrict__ A0, const __half* __restrict__ A1,
    const __half* __restrict__ Wt, int wstride, int ntiles,
    const float* __restrict__ bias, int act,
    __half* __restrict__ out16, float* __restrict__ out32, int ncols)
{
    __shared__ uint32_t Asu[2][BM * AW];
    __shared__ uint32_t Bsu[2][BM * AW];
    const int tid = threadIdx.x;
    const int bm = blockIdx.y * BM;
    const int bn = blockIdx.x * BM;
    const int lane = tid & 31, warp = tid >> 5;
    const int g = lane >> 2, tig = lane & 3;
    const int am0 = (warp >> 1) * 64, bn0 = (warp & 1) * 64;

    const __half* a0 = A0 + (size_t)(bm + tid) * KP;
    const __half* a1 = A1 ? (A1 + (size_t)(bm + tid) * KP) : nullptr;
    const __half* wr = Wt + (size_t)(bn + tid) * wstride;

    const uint32_t abase = s2u(&Asu[0][0]);
    const uint32_t bbase = s2u(&Bsu[0][0]);

    float acc[4][8][4];
#pragma unroll
    for (int mt = 0; mt < 4; mt++)
#pragma unroll
        for (int nt = 0; nt < 8; nt++)
#pragma unroll
            for (int r = 0; r < 4; r++) acc[mt][nt][r] = 0.f;

    auto issue = [&](int tt, int buf) {
        const __half* src = (tt < 16) ? (a0 + tt * 32) : (a1 + (tt - 16) * 32);
        const uint32_t ad = abase + buf * (BM * AW * 4) + tid * (AW * 4);
#pragma unroll
        for (int q = 0; q < 4; q++) cpa16(ad + q * 16, src + q * 8);
        const __half* ws = wr + tt * 32;
        const uint32_t bd = bbase + buf * (BM * AW * 4) + tid * (AW * 4);
#pragma unroll
        for (int q = 0; q < 4; q++) cpa16(bd + q * 16, ws + q * 8);
        cpa_commit();
    };

    issue(0, 0);
    for (int tt = 0; tt < ntiles; tt++) {
        const int buf = tt & 1;
        const bool more = tt + 1 < ntiles;
        if (more) { issue(tt + 1, buf ^ 1); cpa_wait<1>(); } else cpa_wait<0>();
        __syncthreads();
        const uint32_t* Au = Asu[buf];
        const uint32_t* Bu = Bsu[buf];
#pragma unroll
        for (int s = 0; s < 2; s++) {
            const int wb = s * 8;
            uint32_t fa[4][4], fb[8][2];
#pragma unroll
            for (int mt = 0; mt < 4; mt++) {
                const int r = am0 + mt * 16 + g;
                fa[mt][0] = Au[r * AW + wb + tig];
                fa[mt][1] = Au[(r + 8) * AW + wb + tig];
                fa[mt][2] = Au[r * AW + wb + tig + 4];
                fa[mt][3] = Au[(r + 8) * AW + wb + tig + 4];
            }
#pragma unroll
            for (int nt = 0; nt < 8; nt++) {
                const int cn = bn0 + nt * 8 + g;
                fb[nt][0] = Bu[cn * AW + wb + tig];
                fb[nt][1] = Bu[cn * AW + wb + tig + 4];
            }
#pragma unroll
            for (int mt = 0; mt < 4; mt++)
#pragma unroll
                for (int nt = 0; nt < 8; nt++)
                    mma16(acc[mt][nt], fa[mt], fb[nt]);
        }
        __syncthreads();
    }

#pragma unroll
    for (int mt = 0; mt < 4; mt++) {
        const int row0 = bm + am0 + mt * 16 + g;
#pragma unroll
        for (int nt = 0; nt < 8; nt++) {
            const int col = bn + bn0 + nt * 8 + 2 * tig;
            if (col < ncols) {
                float ba = 0.f, bb = 0.f;
                if (bias) { ba = bias[col]; bb = bias[col + 1]; }
                float v0 = acc[mt][nt][0] + ba;
                float v1 = acc[mt][nt][1] + bb;
                float v2 = acc[mt][nt][2] + ba;
                float v3 = acc[mt][nt][3] + bb;
                if (act) {
                    v0 = fmaxf(v0, 0.f); v1 = fmaxf(v1, 0.f);
                    v2 = fmaxf(v2, 0.f); v3 = fmaxf(v3, 0.f);
                }
                if (out16) {
                    out16[(size_t)row0 * KP + col] = __float2half(v0);
                    out16[(size_t)row0 * KP + col + 1] = __float2half(v1);
                    out16[(size_t)(row0 + 8) * KP + col] = __float2half(v2);
                    out16[(size_t)(row0 + 8) * KP + col + 1] = __float2half(v3);
                } else {
                    *reinterpret_cast<float2*>(&out32[(size_t)row0 * ncols + col]) = make_float2(v0, v1);
                    *reinterpret_cast<float2*>(&out32[(size_t)(row0 + 8) * ncols + col]) = make_float2(v2, v3);
                }
            }
        }
    }
}

// ---------------- GAT attention scores ----------------
__global__ void gat_scores_k(const float* __restrict__ al, const float* __restrict__ ar) {
    int w = (blockIdx.x * blockDim.x + threadIdx.x) >> 5;
    int lane = threadIdx.x & 31;
    if (w >= Nn * NHEADS) return;
    int n = w / NHEADS, hd = w % NHEADS;
    const float* zr = g_z + (size_t)n * NZ + hd * Hh;
    float sl = 0.f, sr = 0.f;
    for (int c = lane; c < Hh; c += 32) {
        float zv = zr[c];
        sl = fmaf(zv, al[hd * Hh + c], sl);
        sr = fmaf(zv, ar[hd * Hh + c], sr);
    }
#pragma unroll
    for (int o = 16; o; o >>= 1) {
        sl += __shfl_xor_sync(0xFFFFFFFFu, sl, o);
        sr += __shfl_xor_sync(0xFFFFFFFFu, sr, o);
    }
    if (lane == 0) { g_el[w] = sl; g_er[w] = sr; }
}

// ---------------- fused GAT aggregate + relu + head-mean + elu + readout + segsum ----------------
__global__ __launch_bounds__(256) void gat_final_k(
    const int* __restrict__ nbr, const int* __restrict__ gid,
    const float* __restrict__ Wr, const float* __restrict__ br,
    float* __restrict__ out)
{
    int n = blockIdx.x;
    int tid = threadIdx.x;
    __shared__ float alpha[NHEADS][Dd];
    __shared__ int nb[Dd];
    __shared__ float red[256];

    if (tid < Dd) nb[tid] = nbr[n * Dd + tid];
    __syncthreads();

    if (tid < NHEADS * Dd) {
        int hd = tid / Dd, d = tid % Dd;
        float e = g_el[nb[d] * NHEADS + hd] + g_er[n * NHEADS + hd];
        alpha[hd][d] = (e > 0.f) ? e : 0.2f * e;
    }
    __syncthreads();
    if (tid < NHEADS) {
        float mx = -1e30f;
#pragma unroll
        for (int d = 0; d < Dd; d++) mx = fmaxf(mx, alpha[tid][d]);
        float ex[Dd]; float s = 0.f;
#pragma unroll
        for (int d = 0; d < Dd; d++) { ex[d] = expf(alpha[tid][d] - mx); s += ex[d]; }
        float inv = 1.f / s;
#pragma unroll
        for (int d = 0; d < Dd; d++) alpha[tid][d] = ex[d] * inv;
    }
    __syncthreads();

    float accum = 0.f;
    for (int c = tid; c < Hh; c += 256) {
        float mean = 0.f;
#pragma unroll
        for (int hd = 0; hd < NHEADS; hd++) {
            float s = 0.f;
#pragma unroll
            for (int d = 0; d < Dd; d++)
                s = fmaf(alpha[hd][d], g_z[(size_t)nb[d] * NZ + hd * Hh + c], s);
            mean += fmaxf(s, 0.f);
        }
        mean *= (1.f / NHEADS);
        float e = (mean > 0.f) ? mean : (expf(mean) - 1.f);
        accum = fmaf(e, Wr[c], accum);
    }
    red[tid] = accum;
    __syncthreads();
    for (int s = 128; s > 0; s >>= 1) {
        if (tid < s) red[tid] += red[tid + s];
        __syncthreads();
    }
    if (tid == 0) atomicAdd(&out[gid[n]], red[0] + br[0]);
}

// ---------------- launch ----------------
extern "C" void kernel_launch(void* const* d_in, const int* in_sizes, int n_in,
                              void* d_out, int out_size) {
    const int* node_ids  = (const int*)d_in[0];
    const int* neighbors = (const int*)d_in[1];
    const int* graph_ids = (const int*)d_in[2];
    const float* emb = (const float*)d_in[4];
    const float* W[3][7];
    int p = 5;
    for (int l = 0; l < 3; l++)
        for (int q = 0; q < 7; q++) W[l][q] = (const float*)d_in[p++];
    const float* Wg = (const float*)d_in[p++];
    const float* al = (const float*)d_in[p++];
    const float* ar = (const float*)d_in[p++];
    const float* Wr = (const float*)d_in[p++];
    const float* br = (const float*)d_in[p++];
    float* out = (float*)d_out;

    __half *x16A, *x16B, *h16A, *h16B, *wfc, *wz;
    float *z, *bfc;
    cudaGetSymbolAddress((void**)&x16A, g_x16A);
    cudaGetSymbolAddress((void**)&x16B, g_x16B);
    cudaGetSymbolAddress((void**)&h16A, g_h16A);
    cudaGetSymbolAddress((void**)&h16B, g_h16B);
    cudaGetSymbolAddress((void**)&wfc, g_wfc);
    cudaGetSymbolAddress((void**)&wz, g_wz);
    cudaGetSymbolAddress((void**)&z, g_z);
    cudaGetSymbolAddress((void**)&bfc, g_bfc);

    const int NHP = Nn * KP;          // padded row elems
    zero_k<<<1, 64>>>(out, out_size);
    // zero pads of h buffers and x16B (x16A fully written by embed)
    zero_k<<<(NHP / 2 + 255) / 256, 256>>>((float*)x16B, NHP / 2);
    zero_k<<<(NHP / 2 + 255) / 256, 256>>>((float*)h16A, NHP / 2);
    zero_k<<<(NHP / 2 + 255) / 256, 256>>>((float*)h16B, NHP / 2);
    embed16_k<<<(NHP + 255) / 256, 256>>>(node_ids, emb);
    build_wz_k<<<(NPZ * 512 + 255) / 256, 256>>>(Wg);

    dim3 gGates(NPG / BM, Nn / BM);    // 16 x 32
    dim3 gFc(NPF / BM, Nn / BM);       // 4 x 32
    dim3 gZ(NPZ / BM, Nn / BM);        // 20 x 32

    __half* xin = x16A;
    __half* xout = x16B;
    for (int l = 0; l < 3; l++) {
        build_wg_k<<<(NPG * 1024 + 255) / 256, 256>>>(W[l][0], W[l][1], W[l][2], W[l][3]);
        build_wfc_k<<<(NPF * 1024 + 255) / 256, 256>>>(W[l][4], W[l][5], W[l][6]);
        __half* hin = h16A;
        __half* hout = h16B;
        for (int t = 0; t < Dd; t++) {
            gates16_cell_k<<<gGates, 128>>>(xin, hin, neighbors, t, t == 0 ? 1 : 0, hout);
            __half* tmp = hin; hin = hout; hout = tmp;
        }
        gemm16_k<<<gFc, 128>>>(xin, hin, wfc, 1024, 32, bfc, 1, xout, nullptr, Hh);
        __half* tmp = xin; xin = xout; xout = tmp;
    }

    gemm16_k<<<gZ, 128>>>(xin, nullptr, wz, 512, 16, nullptr, 0, nullptr, z, NZ);
    gat_scores_k<<<(Nn * NHEADS * 32 + 127) / 128, 128>>>(al, ar);
    gat_final_k<<<Nn, 256>>>(neighbors, graph_ids, Wr, br, out);
}

// round 12
// speedup vs baseline: 1.6754x; 1.0804x over previous
#include <cuda_runtime.h>
#include <cuda_fp16.h>
#include <stdint.h>
#include <math.h>

#define Nn 4096
#define Hh 500
#define Dd 8
#define NHEADS 5
#define NG 2000
#define KP 512          // padded K per part (halfs)
#define NPG 2048        // padded gates N
#define NPF 512         // padded fc N
#define NPZ 2560        // padded z N
#define NZ 2500

#define BM 128
#define AW 20           // uint32 words per smem row (40 halfs = 80B, conflict-free)
#define SLOT (BM * AW * 4)          // 10240 B per buffer slot
#define BREG (4 * SLOT)             // B region offset (4 slots of A first)
#define SMEMSZ (8 * SLOT)           // 81920 B total (4 A + 4 B slots)

// ---------------- scratch ----------------
__device__ __half g_x16A[(size_t)Nn * KP];
__device__ __half g_x16B[(size_t)Nn * KP];
__device__ __half g_h16A[(size_t)Nn * KP];
__device__ __half g_h16B[(size_t)Nn * KP];
__device__ float  g_c[(size_t)Nn * Hh];
__device__ __half g_wg[(size_t)NPG * 1024];
__device__ __half g_wfc[(size_t)NPF * 1024];
__device__ __half g_wz[(size_t)NPZ * 512];
__device__ float  g_bpg[NPG];
__device__ float  g_bfc[NPF];
__device__ float  g_z[(size_t)Nn * NZ];
__device__ float  g_el[Nn * NHEADS];
__device__ float  g_er[Nn * NHEADS];

// ---------------- helpers ----------------
__device__ __forceinline__ float sigm(float x) { return 1.f / (1.f + expf(-x)); }
__device__ __forceinline__ uint32_t s2u(const void* p) {
    uint32_t a;
    asm("{ .reg .u64 t; cvta.to.shared.u64 t, %1; cvt.u32.u64 %0, t; }" : "=r"(a) : "l"(p));
    return a;
}
__device__ __forceinline__ void cpa16(uint32_t s, const void* g) {
    asm volatile("cp.async.cg.shared.global [%0], [%1], 16;" :: "r"(s), "l"(g));
}
__device__ __forceinline__ void cpa_commit() {
    asm volatile("cp.async.commit_group;" ::: "memory");
}
template <int N>
__device__ __forceinline__ void cpa_wait() {
    asm volatile("cp.async.wait_group %0;" :: "n"(N) : "memory");
}
__device__ __forceinline__ void ldsm4(uint32_t* r, uint32_t a) {
    asm volatile("ldmatrix.sync.aligned.m8n8.x4.shared.b16 {%0,%1,%2,%3}, [%4];"
        : "=r"(r[0]), "=r"(r[1]), "=r"(r[2]), "=r"(r[3]) : "r"(a));
}
__device__ __forceinline__ void mma16(float c[4], const uint32_t a[4], const uint32_t b[2]) {
    asm volatile(
        "mma.sync.aligned.m16n8k16.row.col.f32.f16.f16.f32 "
        "{%0,%1,%2,%3}, {%4,%5,%6,%7}, {%8,%9}, {%0,%1,%2,%3};"
        : "+f"(c[0]), "+f"(c[1]), "+f"(c[2]), "+f"(c[3])
        : "r"(a[0]), "r"(a[1]), "r"(a[2]), "r"(a[3]), "r"(b[0]), "r"(b[1]));
}

// ---------------- utility kernels ----------------
__global__ void zero_k(float* p, int n) {
    int i = blockIdx.x * blockDim.x + threadIdx.x;
    if (i < n) p[i] = 0.f;
}
__global__ void embed16_k(const int* __restrict__ ids, const float* __restrict__ emb) {
    int i = blockIdx.x * blockDim.x + threadIdx.x;
    if (i < Nn * KP) {
        int n = i >> 9, j = i & 511;
        g_x16A[i] = __float2half(j < Hh ? emb[(size_t)ids[n] * Hh + j] : 0.f);
    }
}
__global__ void build_wg_k(const float* __restrict__ Wih, const float* __restrict__ Whh,
                           const float* __restrict__ bih, const float* __restrict__ bhh) {
    int idx = blockIdx.x * blockDim.x + threadIdx.x;
    if (idx >= NPG * 1024) return;
    int n = idx >> 10, k = idx & 1023;
    float v = 0.f;
    if (n < NG) {
        int gate = n & 3, j = n >> 2, scol = gate * Hh + j;
        if (k < 512) { if (k < Hh) v = Wih[(size_t)k * NG + scol]; }
        else { int kk = k - 512; if (kk < Hh) v = Whh[(size_t)kk * NG + scol]; }
        if (k == 0) g_bpg[n] = bih[scol] + bhh[scol];
    } else if (k == 0) g_bpg[n] = 0.f;
    g_wg[idx] = __float2half(v);
}
__global__ void build_wfc_k(const float* __restrict__ Wself, const float* __restrict__ Wneigh,
                            const float* __restrict__ b) {
    int idx = blockIdx.x * blockDim.x + threadIdx.x;
    if (idx >= NPF * 1024) return;
    int n = idx >> 10, k = idx & 1023;
    float v = 0.f;
    if (n < Hh) {
        if (k < 512) { if (k < Hh) v = Wself[(size_t)k * Hh + n]; }
        else { int kk = k - 512; if (kk < Hh) v = Wneigh[(size_t)kk * Hh + n]; }
        if (k == 0) g_bfc[n] = b[n];
    } else if (k == 0) g_bfc[n] = 0.f;
    g_wfc[idx] = __float2half(v);
}
__global__ void build_wz_k(const float* __restrict__ Wg) {
    int idx = blockIdx.x * blockDim.x + threadIdx.x;
    if (idx >= NPZ * 512) return;
    int n = idx >> 9, k = idx & 511;
    float v = 0.f;
    if (n < NZ && k < Hh) v = Wg[(size_t)k * NZ + n];
    g_wz[idx] = __float2half(v);
}

// ---------------- shared GEMM core ----------------
struct GemmCore {
    uint32_t smb;
    int lane, am0, bn0;
    uint32_t aoff, boff;

    __device__ __forceinline__ void init(uint32_t smem_base, int tid) {
        smb = smem_base;
        lane = tid & 31;
        const int warp = tid >> 5;
        am0 = (warp >> 1) * 64;
        bn0 = (warp & 1) * 64;
        aoff = (uint32_t)((lane & 15) * 80 + ((lane >> 4) & 1) * 16);
        boff = (uint32_t)((((lane >> 4) & 1) * 8 + (lane & 7)) * 80 + ((lane >> 3) & 1) * 16);
    }
    __device__ __forceinline__ void stage(int tid, int buf, const __half* asrc, const __half* bsrc) {
        const uint32_t ad = smb + buf * SLOT + tid * 80;
        const uint32_t bd = smb + BREG + buf * SLOT + tid * 80;
#pragma unroll
        for (int q = 0; q < 4; q++) cpa16(ad + q * 16, asrc + q * 8);
#pragma unroll
        for (int q = 0; q < 4; q++) cpa16(bd + q * 16, bsrc + q * 8);
        cpa_commit();
    }
    __device__ __forceinline__ void compute(int buf, float acc[4][8][4]) {
        const uint32_t aS = smb + buf * SLOT;
        const uint32_t bS = smb + BREG + buf * SLOT;
#pragma unroll
        for (int s = 0; s < 2; s++) {
            uint32_t fa[4][4], fb[8][2];
#pragma unroll
            for (int mt = 0; mt < 4; mt++)
                ldsm4(fa[mt], aS + (uint32_t)((am0 + mt * 16) * 80 + s * 32) + aoff);
#pragma unroll
            for (int ntp = 0; ntp < 4; ntp++) {
                uint32_t rr[4];
                ldsm4(rr, bS + (uint32_t)((bn0 + ntp * 16) * 80 + s * 32) + boff);
                fb[2 * ntp][0] = rr[0]; fb[2 * ntp][1] = rr[1];
                fb[2 * ntp + 1][0] = rr[2]; fb[2 * ntp + 1][1] = rr[3];
            }
#pragma unroll
            for (int mt = 0; mt < 4; mt++)
#pragma unroll
                for (int nt = 0; nt < 8; nt++)
                    mma16(acc[mt][nt], fa[mt], fb[nt]);
        }
    }
};

// ---------------- gates GEMM (fp16 mma) + fused LSTM cell ----------------
__global__ __launch_bounds__(128) void gates16_cell_k(
    const __half* __restrict__ X, const __half* __restrict__ Hin,
    const int* __restrict__ nbr, int t, int first, __half* __restrict__ Hout)
{
    extern __shared__ __align__(128) char dyn_smem[];
    const int tid = threadIdx.x;
    const int bm = blockIdx.y * BM;
    const int bn = blockIdx.x * BM;
    const int g = (tid & 31) >> 2, tig = tid & 3;

    GemmCore core;
    core.init(s2u(dyn_smem), tid);

    const __half* a0 = X + (size_t)nbr[(bm + tid) * Dd + t] * KP;
    const __half* a1 = Hin + (size_t)(bm + tid) * KP;
    const __half* wr = g_wg + (size_t)(bn + tid) * 1024;
    const int ntiles = first ? 16 : 32;

    float acc[4][8][4];
#pragma unroll
    for (int mt = 0; mt < 4; mt++)
#pragma unroll
        for (int nt = 0; nt < 8; nt++)
#pragma unroll
            for (int r = 0; r < 4; r++) acc[mt][nt][r] = 0.f;

    auto asrc = [&](int tt) { return (tt < 16) ? (a0 + tt * 32) : (a1 + (tt - 16) * 32); };

    core.stage(tid, 0, asrc(0), wr);
    if (ntiles > 1) core.stage(tid, 1, asrc(1), wr + 32);

    for (int tt = 0; tt < ntiles; tt++) {
        if (tt + 2 < ntiles) { core.stage(tid, (tt + 2) & 3, asrc(tt + 2), wr + (tt + 2) * 32); cpa_wait<2>(); }
        else if (tt + 2 == ntiles) cpa_wait<1>();
        else cpa_wait<0>();
        __syncthreads();
        core.compute(tt & 3, acc);
    }

    // fused LSTM cell epilogue: cols interleaved 4j+gate.
#pragma unroll
    for (int mt = 0; mt < 4; mt++) {
        const int row0 = bm + core.am0 + mt * 16 + g;
#pragma unroll
        for (int nt = 0; nt < 8; nt++) {
            const int col = bn + core.bn0 + nt * 8 + 2 * tig;
            const bool ok = col < NG;
            float v0 = 0.f, v1 = 0.f, v2 = 0.f, v3 = 0.f;
            if (ok) {
                const float2 bi = *reinterpret_cast<const float2*>(&g_bpg[col]);
                v0 = acc[mt][nt][0] + bi.x;
                v1 = acc[mt][nt][1] + bi.y;
                v2 = acc[mt][nt][2] + bi.x;
                v3 = acc[mt][nt][3] + bi.y;
            }
            float gg0 = __shfl_xor_sync(0xFFFFFFFFu, v0, 1);
            float oo0 = __shfl_xor_sync(0xFFFFFFFFu, v1, 1);
            float gg1 = __shfl_xor_sync(0xFFFFFFFFu, v2, 1);
            float oo1 = __shfl_xor_sync(0xFFFFFFFFu, v3, 1);
            if (ok && (tig & 1) == 0) {
                const int j = col >> 2;
                {
                    float cp = first ? 0.f : g_c[(size_t)row0 * Hh + j];
                    float c = sigm(v1) * cp + sigm(v0) * tanhf(gg0);
                    g_c[(size_t)row0 * Hh + j] = c;
                    Hout[(size_t)row0 * KP + j] = __float2half(sigm(oo0) * tanhf(c));
                }
                {
                    const int r1 = row0 + 8;
                    float cp = first ? 0.f : g_c[(size_t)r1 * Hh + j];
                    float c = sigm(v3) * cp + sigm(v2) * tanhf(gg1);
                    g_c[(size_t)r1 * Hh + j] = c;
                    Hout[(size_t)r1 * KP + j] = __float2half(sigm(oo1) * tanhf(c));
                }
            }
        }
    }
}

// ---------------- generic fp16 GEMM (fc / z) ----------------
__global__ __launch_bounds__(128) void gemm16_k(
    const __half* __restrict__ A0, const __half* __restrict__ A1,
    const __half* __restrict__ Wt, int wstride, int ntiles,
    const float* __restrict__ bias, int act,
    __half* __restrict__ out16, float* __restrict__ out32, int ncols)
{
    extern __shared__ __align__(128) char dyn_smem[];
    const int tid = threadIdx.x;
    const int bm = blockIdx.y * BM;
    const int bn = blockIdx.x * BM;
    const int g = (tid & 31) >> 2, tig = tid & 3;

    GemmCore core;
    core.init(s2u(dyn_smem), tid);

    const __half* a0 = A0 + (size_t)(bm + tid) * KP;
    const __half* a1 = A1 ? (A1 + (size_t)(bm + tid) * KP) : nullptr;
    const __half* wr = Wt + (size_t)(bn + tid) * wstride;

    float acc[4][8][4];
#pragma unroll
    for (int mt = 0; mt < 4; mt++)
#pragma unroll
        for (int nt = 0; nt < 8; nt++)
#pragma unroll
            for (int r = 0; r < 4; r++) acc[mt][nt][r] = 0.f;

    auto asrc = [&](int tt) { return (tt < 16) ? (a0 + tt * 32) : (a1 + (tt - 16) * 32); };

    core.stage(tid, 0, asrc(0), wr);
    if (ntiles > 1) core.stage(tid, 1, asrc(1), wr + 32);

    for (int tt = 0; tt < ntiles; tt++) {
        if (tt + 2 < ntiles) { core.stage(tid, (tt + 2) & 3, asrc(tt + 2), wr + (tt + 2) * 32); cpa_wait<2>(); }
        else if (tt + 2 == ntiles) cpa_wait<1>();
        else cpa_wait<0>();
        __syncthreads();
        core.compute(tt & 3, acc);
    }

#pragma unroll
    for (int mt = 0; mt < 4; mt++) {
        const int row0 = bm + core.am0 + mt * 16 + g;
#pragma unroll
        for (int nt = 0; nt < 8; nt++) {
            const int col = bn + core.bn0 + nt * 8 + 2 * tig;
            if (col < ncols) {
                float ba = 0.f, bb = 0.f;
                if (bias) { ba = bias[col]; bb = bias[col + 1]; }
                float v0 = acc[mt][nt][0] + ba;
                float v1 = acc[mt][nt][1] + bb;
                float v2 = acc[mt][nt][2] + ba;
                float v3 = acc[mt][nt][3] + bb;
                if (act) {
                    v0 = fmaxf(v0, 0.f); v1 = fmaxf(v1, 0.f);
                    v2 = fmaxf(v2, 0.f); v3 = fmaxf(v3, 0.f);
                }
                if (out16) {
                    out16[(size_t)row0 * KP + col] = __float2half(v0);
                    out16[(size_t)row0 * KP + col + 1] = __float2half(v1);
                    out16[(size_t)(row0 + 8) * KP + col] = __float2half(v2);
                    out16[(size_t)(row0 + 8) * KP + col + 1] = __float2half(v3);
                } else {
                    *reinterpret_cast<float2*>(&out32[(size_t)row0 * ncols + col]) = make_float2(v0, v1);
                    *reinterpret_cast<float2*>(&out32[(size_t)(row0 + 8) * ncols + col]) = make_float2(v2, v3);
                }
            }
        }
    }
}

// ---------------- GAT attention scores ----------------
__global__ void gat_scores_k(const float* __restrict__ al, const float* __restrict__ ar) {
    int w = (blockIdx.x * blockDim.x + threadIdx.x) >> 5;
    int lane = threadIdx.x & 31;
    if (w >= Nn * NHEADS) return;
    int n = w / NHEADS, hd = w % NHEADS;
    const float* zr = g_z + (size_t)n * NZ + hd * Hh;
    float sl = 0.f, sr = 0.f;
    for (int c = lane; c < Hh; c += 32) {
        float zv = zr[c];
        sl = fmaf(zv, al[hd * Hh + c], sl);
        sr = fmaf(zv, ar[hd * Hh + c], sr);
    }
#pragma unroll
    for (int o = 16; o; o >>= 1) {
        sl += __shfl_xor_sync(0xFFFFFFFFu, sl, o);
        sr += __shfl_xor_sync(0xFFFFFFFFu, sr, o);
    }
    if (lane == 0) { g_el[w] = sl; g_er[w] = sr; }
}

// ---------------- fused GAT aggregate + relu + head-mean + elu + readout + segsum ----------------
__global__ __launch_bounds__(256) void gat_final_k(
    const int* __restrict__ nbr, const int* __restrict__ gid,
    const float* __restrict__ Wr, const float* __restrict__ br,
    float* __restrict__ out)
{
    int n = blockIdx.x;
    int tid = threadIdx.x;
    __shared__ float alpha[NHEADS][Dd];
    __shared__ int nb[Dd];
    __shared__ float red[256];

    if (tid < Dd) nb[tid] = nbr[n * Dd + tid];
    __syncthreads();

    if (tid < NHEADS * Dd) {
        int hd = tid / Dd, d = tid % Dd;
        float e = g_el[nb[d] * NHEADS + hd] + g_er[n * NHEADS + hd];
        alpha[hd][d] = (e > 0.f) ? e : 0.2f * e;
    }
    __syncthreads();
    if (tid < NHEADS) {
        float mx = -1e30f;
#pragma unroll
        for (int d = 0; d < Dd; d++) mx = fmaxf(mx, alpha[tid][d]);
        float ex[Dd]; float s = 0.f;
#pragma unroll
        for (int d = 0; d < Dd; d++) { ex[d] = expf(alpha[tid][d] - mx); s += ex[d]; }
        float inv = 1.f / s;
#pragma unroll
        for (int d = 0; d < Dd; d++) alpha[tid][d] = ex[d] * inv;
    }
    __syncthreads();

    float accum = 0.f;
    for (int c = tid; c < Hh; c += 256) {
        float mean = 0.f;
#pragma unroll
        for (int hd = 0; hd < NHEADS; hd++) {
            float s = 0.f;
#pragma unroll
            for (int d = 0; d < Dd; d++)
                s = fmaf(alpha[hd][d], g_z[(size_t)nb[d] * NZ + hd * Hh + c], s);
            mean += fmaxf(s, 0.f);
        }
        mean *= (1.f / NHEADS);
        float e = (mean > 0.f) ? mean : (expf(mean) - 1.f);
        accum = fmaf(e, Wr[c], accum);
    }
    red[tid] = accum;
    __syncthreads();
    for (int s = 128; s > 0; s >>= 1) {
        if (tid < s) red[tid] += red[tid + s];
        __syncthreads();
    }
    if (tid == 0) atomicAdd(&out[gid[n]], red[0] + br[0]);
}

// ---------------- launch ----------------
extern "C" void kernel_launch(void* const* d_in, const int* in_sizes, int n_in,
                              void* d_out, int out_size) {
    const int* node_ids  = (const int*)d_in[0];
    const int* neighbors = (const int*)d_in[1];
    const int* graph_ids = (const int*)d_in[2];
    const float* emb = (const float*)d_in[4];
    const float* W[3][7];
    int p = 5;
    for (int l = 0; l < 3; l++)
        for (int q = 0; q < 7; q++) W[l][q] = (const float*)d_in[p++];
    const float* Wg = (const float*)d_in[p++];
    const float* al = (const float*)d_in[p++];
    const float* ar = (const float*)d_in[p++];
    const float* Wr = (const float*)d_in[p++];
    const float* br = (const float*)d_in[p++];
    float* out = (float*)d_out;

    __half *x16A, *x16B, *h16A, *h16B, *wfc, *wz;
    float *z, *bfc;
    cudaGetSymbolAddress((void**)&x16A, g_x16A);
    cudaGetSymbolAddress((void**)&x16B, g_x16B);
    cudaGetSymbolAddress((void**)&h16A, g_h16A);
    cudaGetSymbolAddress((void**)&h16B, g_h16B);
    cudaGetSymbolAddress((void**)&wfc, g_wfc);
    cudaGetSymbolAddress((void**)&wz, g_wz);
    cudaGetSymbolAddress((void**)&z, g_z);
    cudaGetSymbolAddress((void**)&bfc, g_bfc);

    cudaFuncSetAttribute(gates16_cell_k, cudaFuncAttributeMaxDynamicSharedMemorySize, SMEMSZ);
    cudaFuncSetAttribute(gemm16_k, cudaFuncAttributeMaxDynamicSharedMemorySize, SMEMSZ);

    const int NHP = Nn * KP;
    zero_k<<<1, 64>>>(out, out_size);
    zero_k<<<(NHP / 2 + 255) / 256, 256>>>((float*)x16B, NHP / 2);
    zero_k<<<(NHP / 2 + 255) / 256, 256>>>((float*)h16A, NHP / 2);
    zero_k<<<(NHP / 2 + 255) / 256, 256>>>((float*)h16B, NHP / 2);
    embed16_k<<<(NHP + 255) / 256, 256>>>(node_ids, emb);
    build_wz_k<<<(NPZ * 512 + 255) / 256, 256>>>(Wg);

    dim3 gGates(NPG / BM, Nn / BM);    // 16 x 32
    dim3 gFc(NPF / BM, Nn / BM);       // 4 x 32
    dim3 gZ(NPZ / BM, Nn / BM);        // 20 x 32

    __half* xin = x16A;
    __half* xout = x16B;
    for (int l = 0; l < 3; l++) {
        build_wg_k<<<(NPG * 1024 + 255) / 256, 256>>>(W[l][0], W[l][1], W[l][2], W[l][3]);
        build_wfc_k<<<(NPF * 1024 + 255) / 256, 256>>>(W[l][4], W[l][5], W[l][6]);
        __half* hin = h16A;
        __half* hout = h16B;
        for (int t = 0; t < Dd; t++) {
            gates16_cell_k<<<gGates, 128, SMEMSZ>>>(xin, hin, neighbors, t, t == 0 ? 1 : 0, hout);
            __half* tmp = hin; hin = hout; hout = tmp;
        }
        gemm16_k<<<gFc, 128, SMEMSZ>>>(xin, hin, wfc, 1024, 32, bfc, 1, xout, nullptr, Hh);
        __half* tmp = xin; xin = xout; xout = tmp;
    }

    gemm16_k<<<gZ, 128, SMEMSZ>>>(xin, nullptr, wz, 512, 16, nullptr, 0, nullptr, z, NZ);
    gat_scores_k<<<(Nn * NHEADS * 32 + 127) / 128, 128>>>(al, ar);
    gat_final_k<<<Nn, 256>>>(neighbors, graph_ids, Wr, br, out);
}

// round 13
// speedup vs baseline: 1.7166x; 1.0246x over previous
#include <cuda_runtime.h>
#include <cuda_fp16.h>
#include <stdint.h>
#include <math.h>

#define Nn 4096
#define Hh 500
#define Dd 8
#define NHEADS 5
#define NG 2000
#define KP 512          // padded K per part (halfs)
#define NPG 2048        // padded gates N
#define NPF 512         // padded fc N
#define NPZ 2560        // padded z N
#define NZ 2500

#define BM 128
#define AW 20           // uint32 words per smem row (40 halfs = 80B, conflict-free)
#define SLOT (BM * AW * 4)          // 10240 B per buffer slot
#define NSTAGE 3
#define BREG (NSTAGE * SLOT)        // B region offset (3 slots of A first)
#define SMEMSZ (2 * NSTAGE * SLOT)  // 61440 B total (3 A + 3 B slots) -> 3 CTAs/SM

// ---------------- scratch ----------------
__device__ __half g_x16A[(size_t)Nn * KP];
__device__ __half g_x16B[(size_t)Nn * KP];
__device__ __half g_h16A[(size_t)Nn * KP];
__device__ __half g_h16B[(size_t)Nn * KP];
__device__ float  g_c[(size_t)Nn * Hh];
__device__ __half g_wg[(size_t)NPG * 1024];
__device__ __half g_wfc[(size_t)NPF * 1024];
__device__ __half g_wz[(size_t)NPZ * 512];
__device__ float  g_bpg[NPG];
__device__ float  g_bfc[NPF];
__device__ float  g_z[(size_t)Nn * NZ];
__device__ float  g_el[Nn * NHEADS];
__device__ float  g_er[Nn * NHEADS];

// ---------------- helpers ----------------
__device__ __forceinline__ float sigm(float x) { return 1.f / (1.f + expf(-x)); }
__device__ __forceinline__ uint32_t s2u(const void* p) {
    uint32_t a;
    asm("{ .reg .u64 t; cvta.to.shared.u64 t, %1; cvt.u32.u64 %0, t; }" : "=r"(a) : "l"(p));
    return a;
}
__device__ __forceinline__ void cpa16(uint32_t s, const void* g) {
    asm volatile("cp.async.cg.shared.global [%0], [%1], 16;" :: "r"(s), "l"(g));
}
__device__ __forceinline__ void cpa_commit() {
    asm volatile("cp.async.commit_group;" ::: "memory");
}
template <int N>
__device__ __forceinline__ void cpa_wait() {
    asm volatile("cp.async.wait_group %0;" :: "n"(N) : "memory");
}
__device__ __forceinline__ void ldsm4(uint32_t* r, uint32_t a) {
    asm volatile("ldmatrix.sync.aligned.m8n8.x4.shared.b16 {%0,%1,%2,%3}, [%4];"
        : "=r"(r[0]), "=r"(r[1]), "=r"(r[2]), "=r"(r[3]) : "r"(a));
}
__device__ __forceinline__ void mma16(float c[4], const uint32_t a[4], const uint32_t b[2]) {
    asm volatile(
        "mma.sync.aligned.m16n8k16.row.col.f32.f16.f16.f32 "
        "{%0,%1,%2,%3}, {%4,%5,%6,%7}, {%8,%9}, {%0,%1,%2,%3};"
        : "+f"(c[0]), "+f"(c[1]), "+f"(c[2]), "+f"(c[3])
        : "r"(a[0]), "r"(a[1]), "r"(a[2]), "r"(a[3]), "r"(b[0]), "r"(b[1]));
}

// ---------------- utility kernels ----------------
__global__ void zero_k(float* p, int n) {
    int i = blockIdx.x * blockDim.x + threadIdx.x;
    if (i < n) p[i] = 0.f;
}
__global__ void embed16_k(const int* __restrict__ ids, const float* __restrict__ emb) {
    int i = blockIdx.x * blockDim.x + threadIdx.x;
    if (i < Nn * KP) {
        int n = i >> 9, j = i & 511;
        g_x16A[i] = __float2half(j < Hh ? emb[(size_t)ids[n] * Hh + j] : 0.f);
    }
}
__global__ void build_wg_k(const float* __restrict__ Wih, const float* __restrict__ Whh,
                           const float* __restrict__ bih, const float* __restrict__ bhh) {
    int idx = blockIdx.x * blockDim.x + threadIdx.x;
    if (idx >= NPG * 1024) return;
    int n = idx >> 10, k = idx & 1023;
    float v = 0.f;
    if (n < NG) {
        int gate = n & 3, j = n >> 2, scol = gate * Hh + j;
        if (k < 512) { if (k < Hh) v = Wih[(size_t)k * NG + scol]; }
        else { int kk = k - 512; if (kk < Hh) v = Whh[(size_t)kk * NG + scol]; }
        if (k == 0) g_bpg[n] = bih[scol] + bhh[scol];
    } else if (k == 0) g_bpg[n] = 0.f;
    g_wg[idx] = __float2half(v);
}
__global__ void build_wfc_k(const float* __restrict__ Wself, const float* __restrict__ Wneigh,
                            const float* __restrict__ b) {
    int idx = blockIdx.x * blockDim.x + threadIdx.x;
    if (idx >= NPF * 1024) return;
    int n = idx >> 10, k = idx & 1023;
    float v = 0.f;
    if (n < Hh) {
        if (k < 512) { if (k < Hh) v = Wself[(size_t)k * Hh + n]; }
        else { int kk = k - 512; if (kk < Hh) v = Wneigh[(size_t)kk * Hh + n]; }
        if (k == 0) g_bfc[n] = b[n];
    } else if (k == 0) g_bfc[n] = 0.f;
    g_wfc[idx] = __float2half(v);
}
__global__ void build_wz_k(const float* __restrict__ Wg) {
    int idx = blockIdx.x * blockDim.x + threadIdx.x;
    if (idx >= NPZ * 512) return;
    int n = idx >> 9, k = idx & 511;
    float v = 0.f;
    if (n < NZ && k < Hh) v = Wg[(size_t)k * NZ + n];
    g_wz[idx] = __float2half(v);
}

// ---------------- shared GEMM core (3-stage ring, 1-ahead prefetch) ----------------
struct GemmCore {
    uint32_t smb;
    int lane, am0, bn0;
    uint32_t aoff, boff;

    __device__ __forceinline__ void init(uint32_t smem_base, int tid) {
        smb = smem_base;
        lane = tid & 31;
        const int warp = tid >> 5;
        am0 = (warp >> 1) * 64;
        bn0 = (warp & 1) * 64;
        aoff = (uint32_t)((lane & 15) * 80 + ((lane >> 4) & 1) * 16);
        boff = (uint32_t)((((lane >> 4) & 1) * 8 + (lane & 7)) * 80 + ((lane >> 3) & 1) * 16);
    }
    __device__ __forceinline__ void stage(int tid, int buf, const __half* asrc, const __half* bsrc) {
        const uint32_t ad = smb + buf * SLOT + tid * 80;
        const uint32_t bd = smb + BREG + buf * SLOT + tid * 80;
#pragma unroll
        for (int q = 0; q < 4; q++) cpa16(ad + q * 16, asrc + q * 8);
#pragma unroll
        for (int q = 0; q < 4; q++) cpa16(bd + q * 16, bsrc + q * 8);
        cpa_commit();
    }
    __device__ __forceinline__ void compute(int buf, float acc[4][8][4]) {
        const uint32_t aS = smb + buf * SLOT;
        const uint32_t bS = smb + BREG + buf * SLOT;
#pragma unroll
        for (int s = 0; s < 2; s++) {
            uint32_t fa[4][4], fb[8][2];
#pragma unroll
            for (int mt = 0; mt < 4; mt++)
                ldsm4(fa[mt], aS + (uint32_t)((am0 + mt * 16) * 80 + s * 32) + aoff);
#pragma unroll
            for (int ntp = 0; ntp < 4; ntp++) {
                uint32_t rr[4];
                ldsm4(rr, bS + (uint32_t)((bn0 + ntp * 16) * 80 + s * 32) + boff);
                fb[2 * ntp][0] = rr[0]; fb[2 * ntp][1] = rr[1];
                fb[2 * ntp + 1][0] = rr[2]; fb[2 * ntp + 1][1] = rr[3];
            }
#pragma unroll
            for (int mt = 0; mt < 4; mt++)
#pragma unroll
                for (int nt = 0; nt < 8; nt++)
                    mma16(acc[mt][nt], fa[mt], fb[nt]);
        }
    }
};

// ring mainloop: stage tile tt+1 into slot (tt+1)%3; one sync per tile.
// safety: sync(tt-1) guarantees compute(tt-2) done; slot (tt+1)%3 == (tt-2)%3. OK.
#define GEMM_MAINLOOP(core, tid, ntiles, ASRC, BSRC, acc)                      \
    do {                                                                       \
        (core).stage(tid, 0, ASRC(0), BSRC(0));                                \
        int slot = 0;                                                          \
        for (int tt = 0; tt < (ntiles); tt++) {                                \
            if (tt + 1 < (ntiles)) {                                           \
                int ns = (slot == NSTAGE - 1) ? 0 : slot + 1;                  \
                (core).stage(tid, ns, ASRC(tt + 1), BSRC(tt + 1));             \
                cpa_wait<1>();                                                 \
            } else cpa_wait<0>();                                              \
            __syncthreads();                                                   \
            (core).compute(slot, acc);                                         \
            slot = (slot == NSTAGE - 1) ? 0 : slot + 1;                        \
        }                                                                      \
    } while (0)

// ---------------- gates GEMM (fp16 mma) + fused LSTM cell ----------------
__global__ __launch_bounds__(128, 3) void gates16_cell_k(
    const __half* __restrict__ X, const __half* __restrict__ Hin,
    const int* __restrict__ nbr, int t, int first, __half* __restrict__ Hout)
{
    extern __shared__ __align__(128) char dyn_smem[];
    const int tid = threadIdx.x;
    const int bm = blockIdx.y * BM;
    const int bn = blockIdx.x * BM;
    const int g = (tid & 31) >> 2, tig = tid & 3;

    GemmCore core;
    core.init(s2u(dyn_smem), tid);

    const __half* a0 = X + (size_t)nbr[(bm + tid) * Dd + t] * KP;
    const __half* a1 = Hin + (size_t)(bm + tid) * KP;
    const __half* wr = g_wg + (size_t)(bn + tid) * 1024;
    const int ntiles = first ? 16 : 32;

    float acc[4][8][4];
#pragma unroll
    for (int mt = 0; mt < 4; mt++)
#pragma unroll
        for (int nt = 0; nt < 8; nt++)
#pragma unroll
            for (int r = 0; r < 4; r++) acc[mt][nt][r] = 0.f;

    auto ASRC = [&](int tt) { return (tt < 16) ? (a0 + tt * 32) : (a1 + (tt - 16) * 32); };
    auto BSRC = [&](int tt) { return wr + tt * 32; };

    GEMM_MAINLOOP(core, tid, ntiles, ASRC, BSRC, acc);

    // fused LSTM cell epilogue: cols interleaved 4j+gate.
#pragma unroll
    for (int mt = 0; mt < 4; mt++) {
        const int row0 = bm + core.am0 + mt * 16 + g;
#pragma unroll
        for (int nt = 0; nt < 8; nt++) {
            const int col = bn + core.bn0 + nt * 8 + 2 * tig;
            const bool ok = col < NG;
            float v0 = 0.f, v1 = 0.f, v2 = 0.f, v3 = 0.f;
            if (ok) {
                const float2 bi = *reinterpret_cast<const float2*>(&g_bpg[col]);
                v0 = acc[mt][nt][0] + bi.x;
                v1 = acc[mt][nt][1] + bi.y;
                v2 = acc[mt][nt][2] + bi.x;
                v3 = acc[mt][nt][3] + bi.y;
            }
            float gg0 = __shfl_xor_sync(0xFFFFFFFFu, v0, 1);
            float oo0 = __shfl_xor_sync(0xFFFFFFFFu, v1, 1);
            float gg1 = __shfl_xor_sync(0xFFFFFFFFu, v2, 1);
            float oo1 = __shfl_xor_sync(0xFFFFFFFFu, v3, 1);
            if (ok && (tig & 1) == 0) {
                const int j = col >> 2;
                {
                    float cp = first ? 0.f : g_c[(size_t)row0 * Hh + j];
                    float c = sigm(v1) * cp + sigm(v0) * tanhf(gg0);
                    g_c[(size_t)row0 * Hh + j] = c;
                    Hout[(size_t)row0 * KP + j] = __float2half(sigm(oo0) * tanhf(c));
                }
                {
                    const int r1 = row0 + 8;
                    float cp = first ? 0.f : g_c[(size_t)r1 * Hh + j];
                    float c = sigm(v3) * cp + sigm(v2) * tanhf(gg1);
                    g_c[(size_t)r1 * Hh + j] = c;
                    Hout[(size_t)r1 * KP + j] = __float2half(sigm(oo1) * tanhf(c));
                }
            }
        }
    }
}

// ---------------- generic fp16 GEMM (fc / z) ----------------
__global__ __launch_bounds__(128, 3) void gemm16_k(
    const __half* __restrict__ A0, const __half* __restrict__ A1,
    const __half* __restrict__ Wt, int wstride, int ntiles,
    const float* __restrict__ bias, int act,
    __half* __restrict__ out16, float* __restrict__ out32, int ncols)
{
    extern __shared__ __align__(128) char dyn_smem[];
    const int tid = threadIdx.x;
    const int bm = blockIdx.y * BM;
    const int bn = blockIdx.x * BM;
    const int g = (tid & 31) >> 2, tig = tid & 3;

    GemmCore core;
    core.init(s2u(dyn_smem), tid);

    const __half* a0 = A0 + (size_t)(bm + tid) * KP;
    const __half* a1 = A1 ? (A1 + (size_t)(bm + tid) * KP) : nullptr;
    const __half* wr = Wt + (size_t)(bn + tid) * wstride;

    float acc[4][8][4];
#pragma unroll
    for (int mt = 0; mt < 4; mt++)
#pragma unroll
        for (int nt = 0; nt < 8; nt++)
#pragma unroll
            for (int r = 0; r < 4; r++) acc[mt][nt][r] = 0.f;

    auto ASRC = [&](int tt) { return (tt < 16) ? (a0 + tt * 32) : (a1 + (tt - 16) * 32); };
    auto BSRC = [&](int tt) { return wr + tt * 32; };

    GEMM_MAINLOOP(core, tid, ntiles, ASRC, BSRC, acc);

#pragma unroll
    for (int mt = 0; mt < 4; mt++) {
        const int row0 = bm + core.am0 + mt * 16 + g;
#pragma unroll
        for (int nt = 0; nt < 8; nt++) {
            const int col = bn + core.bn0 + nt * 8 + 2 * tig;
            if (col < ncols) {
                float ba = 0.f, bb = 0.f;
                if (bias) { ba = bias[col]; bb = bias[col + 1]; }
                float v0 = acc[mt][nt][0] + ba;
                float v1 = acc[mt][nt][1] + bb;
                float v2 = acc[mt][nt][2] + ba;
                float v3 = acc[mt][nt][3] + bb;
                if (act) {
                    v0 = fmaxf(v0, 0.f); v1 = fmaxf(v1, 0.f);
                    v2 = fmaxf(v2, 0.f); v3 = fmaxf(v3, 0.f);
                }
                if (out16) {
                    out16[(size_t)row0 * KP + col] = __float2half(v0);
                    out16[(size_t)row0 * KP + col + 1] = __float2half(v1);
                    out16[(size_t)(row0 + 8) * KP + col] = __float2half(v2);
                    out16[(size_t)(row0 + 8) * KP + col + 1] = __float2half(v3);
                } else {
                    *reinterpret_cast<float2*>(&out32[(size_t)row0 * ncols + col]) = make_float2(v0, v1);
                    *reinterpret_cast<float2*>(&out32[(size_t)(row0 + 8) * ncols + col]) = make_float2(v2, v3);
                }
            }
        }
    }
}

// ---------------- GAT attention scores ----------------
__global__ void gat_scores_k(const float* __restrict__ al, const float* __restrict__ ar) {
    int w = (blockIdx.x * blockDim.x + threadIdx.x) >> 5;
    int lane = threadIdx.x & 31;
    if (w >= Nn * NHEADS) return;
    int n = w / NHEADS, hd = w % NHEADS;
    const float* zr = g_z + (size_t)n * NZ + hd * Hh;
    float sl = 0.f, sr = 0.f;
    for (int c = lane; c < Hh; c += 32) {
        float zv = zr[c];
        sl = fmaf(zv, al[hd * Hh + c], sl);
        sr = fmaf(zv, ar[hd * Hh + c], sr);
    }
#pragma unroll
    for (int o = 16; o; o >>= 1) {
        sl += __shfl_xor_sync(0xFFFFFFFFu, sl, o);
        sr += __shfl_xor_sync(0xFFFFFFFFu, sr, o);
    }
    if (lane == 0) { g_el[w] = sl; g_er[w] = sr; }
}

// ---------------- fused GAT aggregate + relu + head-mean + elu + readout + segsum ----------------
__global__ __launch_bounds__(256) void gat_final_k(
    const int* __restrict__ nbr, const int* __restrict__ gid,
    const float* __restrict__ Wr, const float* __restrict__ br,
    float* __restrict__ out)
{
    int n = blockIdx.x;
    int tid = threadIdx.x;
    __shared__ float alpha[NHEADS][Dd];
    __shared__ int nb[Dd];
    __shared__ float red[256];

    if (tid < Dd) nb[tid] = nbr[n * Dd + tid];
    __syncthreads();

    if (tid < NHEADS * Dd) {
        int hd = tid / Dd, d = tid % Dd;
        float e = g_el[nb[d] * NHEADS + hd] + g_er[n * NHEADS + hd];
        alpha[hd][d] = (e > 0.f) ? e : 0.2f * e;
    }
    __syncthreads();
    if (tid < NHEADS) {
        float mx = -1e30f;
#pragma unroll
        for (int d = 0; d < Dd; d++) mx = fmaxf(mx, alpha[tid][d]);
        float ex[Dd]; float s = 0.f;
#pragma unroll
        for (int d = 0; d < Dd; d++) { ex[d] = expf(alpha[tid][d] - mx); s += ex[d]; }
        float inv = 1.f / s;
#pragma unroll
        for (int d = 0; d < Dd; d++) alpha[tid][d] = ex[d] * inv;
    }
    __syncthreads();

    float accum = 0.f;
    for (int c = tid; c < Hh; c += 256) {
        float mean = 0.f;
#pragma unroll
        for (int hd = 0; hd < NHEADS; hd++) {
            float s = 0.f;
#pragma unroll
            for (int d = 0; d < Dd; d++)
                s = fmaf(alpha[hd][d], g_z[(size_t)nb[d] * NZ + hd * Hh + c], s);
            mean += fmaxf(s, 0.f);
        }
        mean *= (1.f / NHEADS);
        float e = (mean > 0.f) ? mean : (expf(mean) - 1.f);
        accum = fmaf(e, Wr[c], accum);
    }
    red[tid] = accum;
    __syncthreads();
    for (int s = 128; s > 0; s >>= 1) {
        if (tid < s) red[tid] += red[tid + s];
        __syncthreads();
    }
    if (tid == 0) atomicAdd(&out[gid[n]], red[0] + br[0]);
}

// ---------------- launch ----------------
extern "C" void kernel_launch(void* const* d_in, const int* in_sizes, int n_in,
                              void* d_out, int out_size) {
    const int* node_ids  = (const int*)d_in[0];
    const int* neighbors = (const int*)d_in[1];
    const int* graph_ids = (const int*)d_in[2];
    const float* emb = (const float*)d_in[4];
    const float* W[3][7];
    int p = 5;
    for (int l = 0; l < 3; l++)
        for (int q = 0; q < 7; q++) W[l][q] = (const float*)d_in[p++];
    const float* Wg = (const float*)d_in[p++];
    const float* al = (const float*)d_in[p++];
    const float* ar = (const float*)d_in[p++];
    const float* Wr = (const float*)d_in[p++];
    const float* br = (const float*)d_in[p++];
    float* out = (float*)d_out;

    __half *x16A, *x16B, *h16A, *h16B, *wfc, *wz;
    float *z, *bfc;
    cudaGetSymbolAddress((void**)&x16A, g_x16A);
    cudaGetSymbolAddress((void**)&x16B, g_x16B);
    cudaGetSymbolAddress((void**)&h16A, g_h16A);
    cudaGetSymbolAddress((void**)&h16B, g_h16B);
    cudaGetSymbolAddress((void**)&wfc, g_wfc);
    cudaGetSymbolAddress((void**)&wz, g_wz);
    cudaGetSymbolAddress((void**)&z, g_z);
    cudaGetSymbolAddress((void**)&bfc, g_bfc);

    cudaFuncSetAttribute(gates16_cell_k, cudaFuncAttributeMaxDynamicSharedMemorySize, SMEMSZ);
    cudaFuncSetAttribute(gemm16_k, cudaFuncAttributeMaxDynamicSharedMemorySize, SMEMSZ);

    const int NHP = Nn * KP;
    zero_k<<<1, 64>>>(out, out_size);
    zero_k<<<(NHP / 2 + 255) / 256, 256>>>((float*)x16B, NHP / 2);
    zero_k<<<(NHP / 2 + 255) / 256, 256>>>((float*)h16A, NHP / 2);
    zero_k<<<(NHP / 2 + 255) / 256, 256>>>((float*)h16B, NHP / 2);
    embed16_k<<<(NHP + 255) / 256, 256>>>(node_ids, emb);
    build_wz_k<<<(NPZ * 512 + 255) / 256, 256>>>(Wg);

    dim3 gGates(NPG / BM, Nn / BM);    // 16 x 32
    dim3 gFc(NPF / BM, Nn / BM);       // 4 x 32
    dim3 gZ(NPZ / BM, Nn / BM);        // 20 x 32

    __half* xin = x16A;
    __half* xout = x16B;
    for (int l = 0; l < 3; l++) {
        build_wg_k<<<(NPG * 1024 + 255) / 256, 256>>>(W[l][0], W[l][1], W[l][2], W[l][3]);
        build_wfc_k<<<(NPF * 1024 + 255) / 256, 256>>>(W[l][4], W[l][5], W[l][6]);
        __half* hin = h16A;
        __half* hout = h16B;
        for (int t = 0; t < Dd; t++) {
            gates16_cell_k<<<gGates, 128, SMEMSZ>>>(xin, hin, neighbors, t, t == 0 ? 1 : 0, hout);
            __half* tmp = hin; hin = hout; hout = tmp;
        }
        gemm16_k<<<gFc, 128, SMEMSZ>>>(xin, hin, wfc, 1024, 32, bfc, 1, xout, nullptr, Hh);
        __half* tmp = xin; xin = xout; xout = tmp;
    }

    gemm16_k<<<gZ, 128, SMEMSZ>>>(xin, nullptr, wz, 512, 16, nullptr, 0, nullptr, z, NZ);
    gat_scores_k<<<(Nn * NHEADS * 32 + 127) / 128, 128>>>(al, ar);
    gat_final_k<<<Nn, 256>>>(neighbors, graph_ids, Wr, br, out);
}